// round 11
// baseline (speedup 1.0000x reference)
#include <cuda_runtime.h>
#include <math.h>
#include <cstdint>

#define Bn 4
#define CI 128
#define CO 128
#define Hn 128
#define Wn 128
#define HW (Hn*Wn)
#define KK 9
#define CIP 136          // pixel-row stride; conflict-free for STS.128 and LDS.64
#define SBUF (128*CIP)   // one sample buffer, floats

// packed fp32x2 helpers (for offset conv)
#define PACKF2(d, a, b) asm("mov.b64 %0, {%1, %2};" : "=l"(d) : "f"(a), "f"(b))
#define FMAF2(d, a, b, c) asm("fma.rn.f32x2 %0, %1, %2, %3;" : "=l"(d) : "l"(a), "l"(b), "l"(c))
union F2U { unsigned long long u; float2 f; };

// tf32 convert (round to nearest)
#define CVT_TF32(u, f) asm("cvt.rna.tf32.f32 %0, %1;" : "=r"(u) : "f"(f))

// warp-level tensor core MMA: D(16x8) += A(16x8,tf32) * B(8x8,tf32)
__device__ __forceinline__ void mma_tf32(float* c, const uint4& a, uint32_t b0, uint32_t b1) {
    asm volatile("mma.sync.aligned.m16n8k8.row.col.f32.tf32.tf32.f32 "
        "{%0,%1,%2,%3}, {%4,%5,%6,%7}, {%8,%9}, {%0,%1,%2,%3};"
        : "+f"(c[0]), "+f"(c[1]), "+f"(c[2]), "+f"(c[3])
        : "r"(a.x), "r"(a.y), "r"(a.z), "r"(a.w), "r"(b0), "r"(b1));
}

// channel -> storage position: within each 8-group store order 0,4,1,5,2,6,3,7
__device__ __forceinline__ int permc(int c) {
    return (c & ~7) | (((c & 3) << 1) | ((c >> 2) & 1));
}

// ---------------- scratch ----------------
__device__ __align__(16) float g_xT[Bn*HW*CI];       // x in NHWC, channel-permuted
__device__ __align__(16) float g_offp[2][Bn*18*HW];  // partial offset conv
__device__ __align__(16) float g_wF[KK*16*8*32*4];   // weights in A-fragment order (tf32)
__device__ __align__(16) float g_conv[Bn*CO*HW];     // pre-BN output
__device__ float g_stat[2*CO];                       // fused BN sums: [o]=sum, [128+o]=sumsq
__device__ float g_scale[CO];
__device__ float g_shift[CO];

// ---------------- K1: NCHW -> NHWC (channel-permuted) transpose of x ----------------
__global__ void k_transpose_x(const float* __restrict__ in) {
    __shared__ float t[32][33];
    int wb = blockIdx.x * 32, cb = blockIdx.y * 32;
    int by = blockIdx.z;
    int b = by >> 7, y = by & 127;
    t[threadIdx.y][threadIdx.x] =
        in[((b*CI + cb + threadIdx.y)*Hn + y)*Wn + wb + threadIdx.x];
    __syncthreads();
    g_xT[(by*Wn + wb + threadIdx.y)*CI + permc(cb + threadIdx.x)] = t[threadIdx.x][threadIdx.y];
}

// ---------------- K2: w_dcn -> A-fragment prepack (tf32); also zero g_stat ----------------
__global__ void k_prep_w(const float* __restrict__ w) {
    if (blockIdx.x == 0 && threadIdx.x < 2*CO) g_stat[threadIdx.x] = 0.f;
    int i = blockIdx.x * blockDim.x + threadIdx.x;
    if (i >= KK*16*8*32) return;
    int l = i & 31;
    int r = i >> 5;
    int ost = r & 7;  r >>= 3;
    int s = r & 15;
    int tap = r >> 4;
    int o = ost*16 + (l >> 2);
    int c = s*8 + (l & 3);
    float a0 = w[(o*CI + c)*9 + tap];
    float a1 = w[((o+8)*CI + c)*9 + tap];
    float a2 = w[(o*CI + c + 4)*9 + tap];
    float a3 = w[((o+8)*CI + c + 4)*9 + tap];
    uint4 u;
    CVT_TF32(u.x, a0); CVT_TF32(u.y, a1); CVT_TF32(u.z, a2); CVT_TF32(u.w, a3);
    ((uint4*)g_wF)[i] = u;
}

// ---------------- K3: offset conv (18 out ch, 3x3, pad 1), CI split over z ----------------
__global__ __launch_bounds__(128) void k_offset_conv(
    const float* __restrict__ x, const float* __restrict__ w_off,
    const float* __restrict__ b_off) {
    __shared__ __align__(16) float sw[64*9*18];
    int h = blockIdx.x, b = blockIdx.y, z = blockIdx.z;
    int c0 = z * 64;
    int w = threadIdx.x;

    unsigned long long acc2[9];
#pragma unroll
    for (int j = 0; j < 9; j++) acc2[j] = 0ull;

    for (int e = threadIdx.x; e < 64*9*18; e += 128) {
        int cl = e / 162, r = e % 162, t = r / 18, j = r % 18;
        sw[e] = w_off[((j*CI + c0 + cl)*3 + t/3)*3 + t%3];
    }
    __syncthreads();
    for (int cl = 0; cl < 64; cl++) {
        const float* xp = x + (size_t)(b*CI + c0 + cl)*HW;
#pragma unroll
        for (int t = 0; t < 9; t++) {
            int yy = h + t/3 - 1;
            int xx = w + t%3 - 1;
            float xv = (yy >= 0 && yy < Hn && xx >= 0 && xx < Wn)
                     ? xp[yy*Wn + xx] : 0.f;
            unsigned long long xv2;
            PACKF2(xv2, xv, xv);
            const unsigned long long* swp =
                (const unsigned long long*)&sw[(cl*9 + t)*18];
#pragma unroll
            for (int j = 0; j < 9; j++) FMAF2(acc2[j], xv2, swp[j], acc2[j]);
        }
    }
#pragma unroll
    for (int jj = 0; jj < 9; jj++) {
        F2U u; u.u = acc2[jj];
        float b0 = (z == 0) ? b_off[2*jj]     : 0.f;
        float b1 = (z == 0) ? b_off[2*jj + 1] : 0.f;
        g_offp[z][((b*18 + 2*jj    )*Hn + h)*Wn + w] = u.f.x + b0;
        g_offp[z][((b*18 + 2*jj + 1)*Hn + h)*Wn + w] = u.f.y + b1;
    }
}

// ---------------- K4: warp-specialized sampling || TF32 MMA, double-buffered ----------------
// block = (h, b): 128 pixels x 128 out channels. 512 threads = 16 warps.
// warps 0-7: MMA (wm = wid>>1 -> 32 o, wc = wid&1 -> 64 px);
// warps 8-15: samplers (fill next tap's buffer while MMA consumes current).
__global__ __launch_bounds__(512, 1) void k_main() {
    extern __shared__ __align__(16) char smem[];
    float* sB = (float*)smem;                 // [2][SBUF]

    const int h   = blockIdx.x;
    const int b   = blockIdx.y;
    const int tid = threadIdx.x;
    const int wid = tid >> 5;
    const int l   = tid & 31;
    const bool is_mma = (wid < 8);
    const int wm  = (wid >> 1) & 3;
    const int wc  = wid & 1;

    // sampler role indices (warps 8-15 -> stid 0..255)
    const int stid = tid & 255;
    const int spix = stid >> 3;               // pixel 0..31 per pass
    const int sc   = (stid & 7) * 4;          // channel-position quad base

    float acc[2][8][4];
#pragma unroll
    for (int st = 0; st < 2; st++)
#pragma unroll
        for (int t = 0; t < 8; t++)
#pragma unroll
            for (int j = 0; j < 4; j++) acc[st][t][j] = 0.f;

    // ---- sampler: fill one tap into dst ----
    auto sample_tap = [&](int k, float* dst) {
        const int ky = k / 3, kx = k % 3;
        const int obase = ((b*18 + 2*k)*Hn + h)*Wn;
#pragma unroll
        for (int pass = 0; pass < 4; pass++) {
            int px = pass*32 + spix;
            float dy = g_offp[0][obase + px]      + g_offp[1][obase + px];
            float dx = g_offp[0][obase + HW + px] + g_offp[1][obase + HW + px];
            float ys = (float)(h - 1 + ky) + dy;
            float xs = (float)(px - 1 + kx) + dx;
            float y0f = floorf(ys), x0f = floorf(xs);
            float wy = ys - y0f, wx = xs - x0f;
            int y0 = (int)y0f, x0 = (int)x0f;
            int y1 = y0 + 1, x1 = x0 + 1;
            float vy0 = (y0 >= 0 && y0 < Hn) ? 1.f : 0.f;
            float vy1 = (y1 >= 0 && y1 < Hn) ? 1.f : 0.f;
            float vx0 = (x0 >= 0 && x0 < Wn) ? 1.f : 0.f;
            float vx1 = (x1 >= 0 && x1 < Wn) ? 1.f : 0.f;
            int y0c = min(max(y0, 0), Hn-1), y1c = min(max(y1, 0), Hn-1);
            int x0c = min(max(x0, 0), Wn-1), x1c = min(max(x1, 0), Wn-1);
            int base = b * HW;
            int i0 = (base + y0c*Wn + x0c)*CI;
            int i1 = (base + y0c*Wn + x1c)*CI;
            int i2 = (base + y1c*Wn + x0c)*CI;
            int i3 = (base + y1c*Wn + x1c)*CI;
            float w00 = (1.f - wy)*(1.f - wx)*vy0*vx0;
            float w01 = (1.f - wy)*wx       *vy0*vx1;
            float w10 = wy       *(1.f - wx)*vy1*vx0;
            float w11 = wy       *wx        *vy1*vx1;
#pragma unroll
            for (int cc = 0; cc < CI; cc += 32) {
                int c = cc + sc;
                float4 p0 = *(const float4*)(g_xT + i0 + c);
                float4 p1 = *(const float4*)(g_xT + i1 + c);
                float4 p2 = *(const float4*)(g_xT + i2 + c);
                float4 p3 = *(const float4*)(g_xT + i3 + c);
                float4 v;
                v.x = w00*p0.x + w01*p1.x + w10*p2.x + w11*p3.x;
                v.y = w00*p0.y + w01*p1.y + w10*p2.y + w11*p3.y;
                v.z = w00*p0.z + w01*p1.z + w10*p2.z + w11*p3.z;
                v.w = w00*p0.w + w01*p1.w + w10*p2.w + w11*p3.w;
                uint4 u;
                CVT_TF32(u.x, v.x); CVT_TF32(u.y, v.y);
                CVT_TF32(u.z, v.z); CVT_TF32(u.w, v.w);
                *(uint4*)(dst + px*CIP + c) = u;
            }
        }
    };

    // prologue: samplers fill buffer 0
    if (!is_mma) sample_tap(0, sB);
    __syncthreads();

    for (int k = 0; k < KK; k++) {
        if (is_mma) {
            // --- GEMM tap k: 16 K=8 steps; per step 2 A-frag LDG.128 + 8 B LDS.64 ---
            const float* bBase = sB + (k & 1)*SBUF
                               + (wc*64 + (l >> 2))*CIP + (l & 3)*2;
            const uint4* aBase = (const uint4*)g_wF + ((k*16)*8 + 2*wm)*32 + l;
#pragma unroll 2
            for (int s = 0; s < 16; s++) {
                uint4 aF0 = aBase[s*256];          // ostripe 2*wm
                uint4 aF1 = aBase[s*256 + 32];     // ostripe 2*wm + 1
                const float* bp = bBase + s*8;
#pragma unroll
                for (int t = 0; t < 8; t++) {
                    uint2 bv = *(const uint2*)(bp + t*8*CIP);
                    mma_tf32(acc[0][t], aF0, bv.x, bv.y);
                    mma_tf32(acc[1][t], aF1, bv.x, bv.y);
                }
            }
        } else if (k + 1 < KK) {
            sample_tap(k + 1, sB + ((k + 1) & 1)*SBUF);
        }
        __syncthreads();
    }

    if (is_mma) {
        // --- epilogue: D[o][pix] fragments -> g_conv (NCHW) ---
#pragma unroll
        for (int st = 0; st < 2; st++) {
            int o = 32*wm + st*16 + (l >> 2);
#pragma unroll
            for (int t = 0; t < 8; t++) {
                int px = wc*64 + t*8 + 2*(l & 3);
                float* d = g_conv + ((size_t)(b*CO + o)*Hn + h)*Wn + px;
                *(float2*)d          = make_float2(acc[st][t][0], acc[st][t][1]);
                *(float2*)(d + 8*HW) = make_float2(acc[st][t][2], acc[st][t][3]);
            }
        }
        // --- fused BN stats: quad-reduce, atomic ---
        float s[4] = {0.f, 0.f, 0.f, 0.f};
        float q[4] = {0.f, 0.f, 0.f, 0.f};
#pragma unroll
        for (int st = 0; st < 2; st++)
#pragma unroll
            for (int t = 0; t < 8; t++) {
                float a0 = acc[st][t][0], a1 = acc[st][t][1];
                float a2 = acc[st][t][2], a3 = acc[st][t][3];
                s[2*st]   += a0 + a1;  q[2*st]   += a0*a0 + a1*a1;
                s[2*st+1] += a2 + a3;  q[2*st+1] += a2*a2 + a3*a3;
            }
#pragma unroll
        for (int d = 1; d < 4; d <<= 1)
#pragma unroll
            for (int j = 0; j < 4; j++) {
                s[j] += __shfl_xor_sync(0xffffffffu, s[j], d);
                q[j] += __shfl_xor_sync(0xffffffffu, q[j], d);
            }
        if ((l & 3) == 0) {
            int o0 = 32*wm + (l >> 2);
#pragma unroll
            for (int j = 0; j < 4; j++) {
                int o = o0 + 8*j;
                atomicAdd(&g_stat[o], s[j]);
                atomicAdd(&g_stat[CO + o], q[j]);
            }
        }
    }
}

// ---------------- K5: BN finalize (tiny) ----------------
__global__ void k_bn_finalize(const float* __restrict__ gamma,
                              const float* __restrict__ beta) {
    int o = threadIdx.x;
    float inv_n = 1.f / (float)(Bn*HW);
    float mean = g_stat[o] * inv_n;
    float var  = g_stat[CO + o] * inv_n - mean*mean;
    float r = rsqrtf(var + 0.001f);
    float sc = gamma[o] * r;
    g_scale[o] = sc;
    g_shift[o] = beta[o] - mean*sc;
}

// ---------------- K6: apply BN + ReLU ----------------
__global__ void k_bn_apply(float* __restrict__ out) {
    int i = blockIdx.x * blockDim.x + threadIdx.x;
    int ch = (i >> 12) & 127;
    float4 v = ((const float4*)g_conv)[i];
    float sc = g_scale[ch], sh = g_shift[ch];
    v.x = fmaxf(fmaf(v.x, sc, sh), 0.f);
    v.y = fmaxf(fmaf(v.y, sc, sh), 0.f);
    v.z = fmaxf(fmaf(v.z, sc, sh), 0.f);
    v.w = fmaxf(fmaf(v.w, sc, sh), 0.f);
    ((float4*)out)[i] = v;
}

// ---------------- launch ----------------
extern "C" void kernel_launch(void* const* d_in, const int* in_sizes, int n_in,
                              void* d_out, int out_size) {
    const float* x     = (const float*)d_in[0];
    const float* w_off = (const float*)d_in[1];
    const float* b_off = (const float*)d_in[2];
    const float* w_dcn = (const float*)d_in[3];
    const float* gamma = (const float*)d_in[4];
    const float* beta  = (const float*)d_in[5];
    float* out = (float*)d_out;

    const int smem_k4 = 2*SBUF*4;
    cudaFuncSetAttribute(k_main, cudaFuncAttributeMaxDynamicSharedMemorySize, smem_k4);

    k_transpose_x<<<dim3(Wn/32, CI/32, Bn*Hn), dim3(32, 32)>>>(x);
    k_prep_w<<<(KK*16*8*32 + 255)/256, 256>>>(w_dcn);
    k_offset_conv<<<dim3(Hn, Bn, 2), 128>>>(x, w_off, b_off);
    k_main<<<dim3(Hn, Bn), 512, smem_k4>>>();
    k_bn_finalize<<<1, CO>>>(gamma, beta);
    k_bn_apply<<<(Bn*CO*HW/4)/256, 256>>>(out);
}

// round 12
// speedup vs baseline: 1.2815x; 1.2815x over previous
#include <cuda_runtime.h>
#include <math.h>
#include <cstdint>

#define Bn 4
#define CI 128
#define CO 128
#define Hn 128
#define Wn 128
#define HW (Hn*Wn)
#define KK 9
#define CIP 136          // pixel-row stride; conflict-free for STS.128 and LDS.64

// tf32 convert (round to nearest)
#define CVT_TF32(u, f) asm("cvt.rna.tf32.f32 %0, %1;" : "=r"(u) : "f"(f))

// warp-level tensor core MMA: D(16x8) += A(16x8,tf32) * B(8x8,tf32)
__device__ __forceinline__ void mma_tf32(float* c, const uint4& a, uint32_t b0, uint32_t b1) {
    asm volatile("mma.sync.aligned.m16n8k8.row.col.f32.tf32.tf32.f32 "
        "{%0,%1,%2,%3}, {%4,%5,%6,%7}, {%8,%9}, {%0,%1,%2,%3};"
        : "+f"(c[0]), "+f"(c[1]), "+f"(c[2]), "+f"(c[3])
        : "r"(a.x), "r"(a.y), "r"(a.z), "r"(a.w), "r"(b0), "r"(b1));
}

// channel -> storage position: within each 8-group store order 0,4,1,5,2,6,3,7
__device__ __forceinline__ int permc(int c) {
    return (c & ~7) | (((c & 3) << 1) | ((c >> 2) & 1));
}

// ---------------- scratch ----------------
__device__ __align__(16) float g_xT[Bn*HW*CI];       // x in NHWC, channel-permuted
__device__ __align__(16) float g_off[Bn*18*HW];      // offset conv output (bias included)
__device__ __align__(16) float g_wF[KK*16*8*32*4];   // w_dcn in A-fragment order (tf32)
__device__ __align__(16) float g_wOffF[KK*16*2*32*4];// w_off in A-fragment order (tf32, M=32 pad)
__device__ __align__(16) float g_conv[Bn*CO*HW];     // pre-BN output
__device__ float g_stat[2*CO];                       // fused BN sums
__device__ float g_scale[CO];
__device__ float g_shift[CO];

// ---------------- K1: NCHW -> NHWC (channel-permuted) transpose of x ----------------
__global__ void k_transpose_x(const float* __restrict__ in) {
    __shared__ float t[32][33];
    int wb = blockIdx.x * 32, cb = blockIdx.y * 32;
    int by = blockIdx.z;
    int b = by >> 7, y = by & 127;
    t[threadIdx.y][threadIdx.x] =
        in[((b*CI + cb + threadIdx.y)*Hn + y)*Wn + wb + threadIdx.x];
    __syncthreads();
    g_xT[(by*Wn + wb + threadIdx.y)*CI + permc(cb + threadIdx.x)] = t[threadIdx.x][threadIdx.y];
}

// ---------------- K2a: w_dcn -> A-fragment prepack (tf32); also zero g_stat ----------------
__global__ void k_prep_w(const float* __restrict__ w) {
    if (blockIdx.x == 0 && threadIdx.x < 2*CO) g_stat[threadIdx.x] = 0.f;
    int i = blockIdx.x * blockDim.x + threadIdx.x;
    if (i >= KK*16*8*32) return;
    int l = i & 31;
    int r = i >> 5;
    int ost = r & 7;  r >>= 3;
    int s = r & 15;
    int tap = r >> 4;
    int o = ost*16 + (l >> 2);
    int c = s*8 + (l & 3);
    float a0 = w[(o*CI + c)*9 + tap];
    float a1 = w[((o+8)*CI + c)*9 + tap];
    float a2 = w[(o*CI + c + 4)*9 + tap];
    float a3 = w[((o+8)*CI + c + 4)*9 + tap];
    uint4 u;
    CVT_TF32(u.x, a0); CVT_TF32(u.y, a1); CVT_TF32(u.z, a2); CVT_TF32(u.w, a3);
    ((uint4*)g_wF)[i] = u;
}

// ---------------- K2b: w_off -> A-fragment prepack (tf32, 18 rows padded to 32) ----------------
// index: ((tap*16 + s)*2 + ost)*32 + lane
__global__ void k_prep_woff(const float* __restrict__ w) {
    int i = blockIdx.x * blockDim.x + threadIdx.x;
    if (i >= KK*16*2*32) return;
    int l   = i & 31;
    int ost = (i >> 5) & 1;
    int s   = (i >> 6) & 15;
    int tap = i >> 10;
    int o = ost*16 + (l >> 2);
    int c = s*8 + (l & 3);
    float a0 = (o     < 18) ? w[(o*CI + c)*9 + tap]         : 0.f;
    float a1 = (o + 8 < 18) ? w[((o+8)*CI + c)*9 + tap]     : 0.f;
    float a2 = (o     < 18) ? w[(o*CI + c + 4)*9 + tap]     : 0.f;
    float a3 = (o + 8 < 18) ? w[((o+8)*CI + c + 4)*9 + tap] : 0.f;
    uint4 u;
    CVT_TF32(u.x, a0); CVT_TF32(u.y, a1); CVT_TF32(u.z, a2); CVT_TF32(u.w, a3);
    ((uint4*)g_wOffF)[i] = u;
}

// ---------------- K3: offset conv via mma.sync (fixed 3x3 sampling from g_xT) ----------------
// block (h, b), 256 threads = 8 warps: wo = wid>>2 (2 o-stripes of 16), wp = wid&3 (32 px).
__global__ __launch_bounds__(256, 2) void k_off_mma(const float* __restrict__ b_off) {
    extern __shared__ __align__(16) char smem[];
    float* sX = (float*)smem;                 // [128 px][CIP] tf32 bits

    const int h   = blockIdx.x;
    const int b   = blockIdx.y;
    const int tid = threadIdx.x;
    const int wid = tid >> 5;
    const int l   = tid & 31;
    const int wo  = wid >> 2;
    const int wp  = wid & 3;

    float acc[4][4];
#pragma unroll
    for (int t = 0; t < 4; t++)
#pragma unroll
        for (int j = 0; j < 4; j++) acc[t][j] = 0.f;

    const float* bBase = sX + (wp*32 + (l >> 2))*CIP + (l & 3)*2;

    for (int k = 0; k < KK; k++) {
        if (k) __syncthreads();
        const int yy = h - 1 + k/3;
        const int kx = k % 3;
        const bool yok = (yy >= 0 && yy < Hn);
        // copy shifted row of g_xT into sX (zero-pad borders), tf32-convert
        for (int i = tid; i < 128*32; i += 256) {
            int px = i >> 5, q = i & 31;
            int sx = px - 1 + kx;
            uint4 u = make_uint4(0u, 0u, 0u, 0u);
            if (yok && sx >= 0 && sx < Wn) {
                float4 v = *(const float4*)(g_xT + (size_t)((b*HW + yy*Wn + sx)*CI) + q*4);
                CVT_TF32(u.x, v.x); CVT_TF32(u.y, v.y);
                CVT_TF32(u.z, v.z); CVT_TF32(u.w, v.w);
            }
            *(uint4*)(sX + px*CIP + q*4) = u;
        }
        __syncthreads();

        const uint4* aBase = (const uint4*)g_wOffF + ((k*16)*2 + wo)*32 + l;
#pragma unroll 2
        for (int s = 0; s < 16; s++) {
            uint4 aF = aBase[s*64];
            const float* bp = bBase + s*8;
#pragma unroll
            for (int t = 0; t < 4; t++) {
                uint2 bv = *(const uint2*)(bp + t*8*CIP);
                mma_tf32(acc[t], aF, bv.x, bv.y);
            }
        }
    }

    // epilogue: rows o<18 -> g_off (+bias)
    {
        int o0  = wo*16 + (l >> 2);
        int px0 = wp*32 + 2*(l & 3);
        float bo0 = (o0     < 18) ? b_off[o0]     : 0.f;
        float bo1 = (o0 + 8 < 18) ? b_off[o0 + 8] : 0.f;
#pragma unroll
        for (int t = 0; t < 4; t++) {
            int px = px0 + t*8;
            if (o0 < 18) {
                float* d = g_off + (size_t)(b*18 + o0)*HW + h*Wn + px;
                d[0] = acc[t][0] + bo0;
                d[1] = acc[t][1] + bo0;
            }
            if (o0 + 8 < 18) {
                float* d = g_off + (size_t)(b*18 + o0 + 8)*HW + h*Wn + px;
                d[0] = acc[t][2] + bo1;
                d[1] = acc[t][3] + bo1;
            }
        }
    }
}

// ---------------- K4: deformable sampling + mma.sync TF32 GEMM + fused BN stats ----------------
// block = (h, b): 128 pixels x 128 out channels. 256 threads = 8 warps.
// warp grid: wm = wid>>1 (4 M-warps, 32 o), wc = wid&1 (2 N-warps, 64 px, 8 t-tiles).
#define OFF_S    0                       // float [128][CIP] tf32 bits  69632 B
#define OFF_OFF  69632                   // float [18][128] offsets      9216 B
#define SMEM_K4  (OFF_OFF + 9216)

__global__ __launch_bounds__(256, 2) void k_main() {
    extern __shared__ __align__(16) char smem[];
    float* sS   = (float*)(smem + OFF_S);
    float* sOff = (float*)(smem + OFF_OFF);

    const int h   = blockIdx.x;
    const int b   = blockIdx.y;
    const int tid = threadIdx.x;
    const int wid = tid >> 5;
    const int l   = tid & 31;
    const int wm  = wid >> 1;
    const int wc  = wid & 1;

    // --- prefetch per-pixel offsets for all taps (bias already included) ---
    for (int j = tid; j < 18*128; j += 256)
        sOff[j] = g_off[(size_t)(b*18 + (j >> 7))*HW + h*Wn + (j & 127)];

    float acc[2][8][4];
#pragma unroll
    for (int st = 0; st < 2; st++)
#pragma unroll
        for (int t = 0; t < 8; t++)
#pragma unroll
            for (int j = 0; j < 4; j++) acc[st][t][j] = 0.f;

    const int spix = tid >> 3;            // sampler: pixel 0..31 (per pass)
    const int sc   = (tid & 7) * 4;       // sampler: channel-position quad base

    const float* bBase = sS + (wc*64 + (l >> 2))*CIP + (l & 3)*2;

    __syncthreads();                      // sOff ready

    for (int k = 0; k < KK; k++) {
        if (k) __syncthreads();           // protect sS from previous tap's readers
        const int ky = k / 3, kx = k % 3;
        const float* dyp = sOff + (2*k)*128;
        const float* dxp = sOff + (2*k + 1)*128;
#pragma unroll
        for (int pass = 0; pass < 4; pass++) {
            int px = pass*32 + spix;
            float dy = dyp[px];
            float dx = dxp[px];
            float ys = (float)(h - 1 + ky) + dy;
            float xs = (float)(px - 1 + kx) + dx;
            float y0f = floorf(ys), x0f = floorf(xs);
            float wy = ys - y0f, wx = xs - x0f;
            int y0 = (int)y0f, x0 = (int)x0f;
            int y1 = y0 + 1, x1 = x0 + 1;
            float vy0 = (y0 >= 0 && y0 < Hn) ? 1.f : 0.f;
            float vy1 = (y1 >= 0 && y1 < Hn) ? 1.f : 0.f;
            float vx0 = (x0 >= 0 && x0 < Wn) ? 1.f : 0.f;
            float vx1 = (x1 >= 0 && x1 < Wn) ? 1.f : 0.f;
            int y0c = min(max(y0, 0), Hn-1), y1c = min(max(y1, 0), Hn-1);
            int x0c = min(max(x0, 0), Wn-1), x1c = min(max(x1, 0), Wn-1);
            int base = b * HW;
            int i0 = (base + y0c*Wn + x0c)*CI;
            int i1 = (base + y0c*Wn + x1c)*CI;
            int i2 = (base + y1c*Wn + x0c)*CI;
            int i3 = (base + y1c*Wn + x1c)*CI;
            float w00 = (1.f - wy)*(1.f - wx)*vy0*vx0;
            float w01 = (1.f - wy)*wx       *vy0*vx1;
            float w10 = wy       *(1.f - wx)*vy1*vx0;
            float w11 = wy       *wx        *vy1*vx1;
#pragma unroll
            for (int cc = 0; cc < CI; cc += 32) {
                int c = cc + sc;
                float4 p0 = *(const float4*)(g_xT + i0 + c);
                float4 p1 = *(const float4*)(g_xT + i1 + c);
                float4 p2 = *(const float4*)(g_xT + i2 + c);
                float4 p3 = *(const float4*)(g_xT + i3 + c);
                float4 v;
                v.x = w00*p0.x + w01*p1.x + w10*p2.x + w11*p3.x;
                v.y = w00*p0.y + w01*p1.y + w10*p2.y + w11*p3.y;
                v.z = w00*p0.z + w01*p1.z + w10*p2.z + w11*p3.z;
                v.w = w00*p0.w + w01*p1.w + w10*p2.w + w11*p3.w;
                uint4 u;
                CVT_TF32(u.x, v.x); CVT_TF32(u.y, v.y);
                CVT_TF32(u.z, v.z); CVT_TF32(u.w, v.w);
                *(uint4*)(sS + px*CIP + c) = u;
            }
        }
        __syncthreads();

        // --- GEMM: 16 K=8 steps; per step 2 A-frag LDG.128 + 8 B LDS.64 ---
        const uint4* aBase = (const uint4*)g_wF + ((k*16)*8 + 2*wm)*32 + l;
#pragma unroll 2
        for (int s = 0; s < 16; s++) {
            uint4 aF0 = aBase[s*256];          // ostripe 2*wm
            uint4 aF1 = aBase[s*256 + 32];     // ostripe 2*wm + 1
            const float* bp = bBase + s*8;
#pragma unroll
            for (int t = 0; t < 8; t++) {
                uint2 bv = *(const uint2*)(bp + t*8*CIP);
                mma_tf32(acc[0][t], aF0, bv.x, bv.y);
                mma_tf32(acc[1][t], aF1, bv.x, bv.y);
            }
        }
    }

    // --- epilogue: D[o][pix] fragments -> g_conv (NCHW) ---
#pragma unroll
    for (int st = 0; st < 2; st++) {
        int o = 32*wm + st*16 + (l >> 2);
#pragma unroll
        for (int t = 0; t < 8; t++) {
            int px = wc*64 + t*8 + 2*(l & 3);
            float* d = g_conv + ((size_t)(b*CO + o)*Hn + h)*Wn + px;
            *(float2*)d          = make_float2(acc[st][t][0], acc[st][t][1]);
            *(float2*)(d + 8*HW) = make_float2(acc[st][t][2], acc[st][t][3]);
        }
    }

    // --- fused BN stats: quad-reduce, atomic ---
    {
        float s[4] = {0.f, 0.f, 0.f, 0.f};
        float q[4] = {0.f, 0.f, 0.f, 0.f};
#pragma unroll
        for (int st = 0; st < 2; st++)
#pragma unroll
            for (int t = 0; t < 8; t++) {
                float a0 = acc[st][t][0], a1 = acc[st][t][1];
                float a2 = acc[st][t][2], a3 = acc[st][t][3];
                s[2*st]   += a0 + a1;  q[2*st]   += a0*a0 + a1*a1;
                s[2*st+1] += a2 + a3;  q[2*st+1] += a2*a2 + a3*a3;
            }
#pragma unroll
        for (int d = 1; d < 4; d <<= 1)
#pragma unroll
            for (int j = 0; j < 4; j++) {
                s[j] += __shfl_xor_sync(0xffffffffu, s[j], d);
                q[j] += __shfl_xor_sync(0xffffffffu, q[j], d);
            }
        if ((l & 3) == 0) {
            int o0 = 32*wm + (l >> 2);
#pragma unroll
            for (int j = 0; j < 4; j++) {
                int o = o0 + 8*j;
                atomicAdd(&g_stat[o], s[j]);
                atomicAdd(&g_stat[CO + o], q[j]);
            }
        }
    }
}

// ---------------- K5: BN finalize (tiny) ----------------
__global__ void k_bn_finalize(const float* __restrict__ gamma,
                              const float* __restrict__ beta) {
    int o = threadIdx.x;
    float inv_n = 1.f / (float)(Bn*HW);
    float mean = g_stat[o] * inv_n;
    float var  = g_stat[CO + o] * inv_n - mean*mean;
    float r = rsqrtf(var + 0.001f);
    float sc = gamma[o] * r;
    g_scale[o] = sc;
    g_shift[o] = beta[o] - mean*sc;
}

// ---------------- K6: apply BN + ReLU ----------------
__global__ void k_bn_apply(float* __restrict__ out) {
    int i = blockIdx.x * blockDim.x + threadIdx.x;
    int ch = (i >> 12) & 127;
    float4 v = ((const float4*)g_conv)[i];
    float sc = g_scale[ch], sh = g_shift[ch];
    v.x = fmaxf(fmaf(v.x, sc, sh), 0.f);
    v.y = fmaxf(fmaf(v.y, sc, sh), 0.f);
    v.z = fmaxf(fmaf(v.z, sc, sh), 0.f);
    v.w = fmaxf(fmaf(v.w, sc, sh), 0.f);
    ((float4*)out)[i] = v;
}

// ---------------- launch ----------------
extern "C" void kernel_launch(void* const* d_in, const int* in_sizes, int n_in,
                              void* d_out, int out_size) {
    const float* x     = (const float*)d_in[0];
    const float* w_off = (const float*)d_in[1];
    const float* b_off = (const float*)d_in[2];
    const float* w_dcn = (const float*)d_in[3];
    const float* gamma = (const float*)d_in[4];
    const float* beta  = (const float*)d_in[5];
    float* out = (float*)d_out;

    const int smem_off = 128*CIP*4;
    cudaFuncSetAttribute(k_off_mma, cudaFuncAttributeMaxDynamicSharedMemorySize, smem_off);
    cudaFuncSetAttribute(k_main, cudaFuncAttributeMaxDynamicSharedMemorySize, SMEM_K4);

    k_transpose_x<<<dim3(Wn/32, CI/32, Bn*Hn), dim3(32, 32)>>>(x);
    k_prep_w<<<(KK*16*8*32 + 255)/256, 256>>>(w_dcn);
    k_prep_woff<<<(KK*16*2*32 + 255)/256, 256>>>(w_off);
    k_off_mma<<<dim3(Hn, Bn), 256, smem_off>>>(b_off);
    k_main<<<dim3(Hn, Bn), 256, SMEM_K4>>>();
    k_bn_finalize<<<1, CO>>>(gamma, beta);
    k_bn_apply<<<(Bn*CO*HW/4)/256, 256>>>(out);
}

// round 13
// speedup vs baseline: 1.3697x; 1.0688x over previous
#include <cuda_runtime.h>
#include <math.h>
#include <cstdint>

#define Bn 4
#define CI 128
#define CO 128
#define Hn 128
#define Wn 128
#define HW (Hn*Wn)
#define KK 9
#define CIP 136          // pixel-row stride; conflict-free for STS.128 and LDS.64

// tf32 convert (round to nearest)
#define CVT_TF32(u, f) asm("cvt.rna.tf32.f32 %0, %1;" : "=r"(u) : "f"(f))

// warp-level tensor core MMA: D(16x8) += A(16x8,tf32) * B(8x8,tf32)
__device__ __forceinline__ void mma_tf32(float* c, const uint4& a, uint32_t b0, uint32_t b1) {
    asm volatile("mma.sync.aligned.m16n8k8.row.col.f32.tf32.tf32.f32 "
        "{%0,%1,%2,%3}, {%4,%5,%6,%7}, {%8,%9}, {%0,%1,%2,%3};"
        : "+f"(c[0]), "+f"(c[1]), "+f"(c[2]), "+f"(c[3])
        : "r"(a.x), "r"(a.y), "r"(a.z), "r"(a.w), "r"(b0), "r"(b1));
}

// channel -> storage position: within each 8-group store order 0,4,1,5,2,6,3,7
__device__ __forceinline__ int permc(int c) {
    return (c & ~7) | (((c & 3) << 1) | ((c >> 2) & 1));
}

// ---------------- scratch ----------------
__device__ __align__(16) float g_xT[Bn*HW*CI];       // x in NHWC, channel-permuted
__device__ __align__(16) float g_wF[KK*16*8*32*4];   // w_dcn in A-fragment order (tf32)
__device__ __align__(16) float g_wOffF[KK*16*2*32*4];// w_off in A-fragment order (tf32, M=32 pad)
__device__ __align__(16) float g_conv[Bn*CO*HW];     // pre-BN output
__device__ float g_stat[2*CO];                       // fused BN sums
__device__ float g_scale[CO];
__device__ float g_shift[CO];

// ---------------- K1: NCHW -> NHWC (channel-permuted) transpose of x ----------------
__global__ void k_transpose_x(const float* __restrict__ in) {
    __shared__ float t[32][33];
    int wb = blockIdx.x * 32, cb = blockIdx.y * 32;
    int by = blockIdx.z;
    int b = by >> 7, y = by & 127;
    t[threadIdx.y][threadIdx.x] =
        in[((b*CI + cb + threadIdx.y)*Hn + y)*Wn + wb + threadIdx.x];
    __syncthreads();
    g_xT[(by*Wn + wb + threadIdx.y)*CI + permc(cb + threadIdx.x)] = t[threadIdx.x][threadIdx.y];
}

// ---------------- K2a: w_dcn -> A-fragment prepack (tf32); also zero g_stat ----------------
__global__ void k_prep_w(const float* __restrict__ w) {
    if (blockIdx.x == 0 && threadIdx.x < 2*CO) g_stat[threadIdx.x] = 0.f;
    int i = blockIdx.x * blockDim.x + threadIdx.x;
    if (i >= KK*16*8*32) return;
    int l = i & 31;
    int r = i >> 5;
    int ost = r & 7;  r >>= 3;
    int s = r & 15;
    int tap = r >> 4;
    int o = ost*16 + (l >> 2);
    int c = s*8 + (l & 3);
    float a0 = w[(o*CI + c)*9 + tap];
    float a1 = w[((o+8)*CI + c)*9 + tap];
    float a2 = w[(o*CI + c + 4)*9 + tap];
    float a3 = w[((o+8)*CI + c + 4)*9 + tap];
    uint4 u;
    CVT_TF32(u.x, a0); CVT_TF32(u.y, a1); CVT_TF32(u.z, a2); CVT_TF32(u.w, a3);
    ((uint4*)g_wF)[i] = u;
}

// ---------------- K2b: w_off -> A-fragment prepack (tf32, 18 rows padded to 32) ----------------
// index: ((tap*16 + s)*2 + ost)*32 + lane
__global__ void k_prep_woff(const float* __restrict__ w) {
    int i = blockIdx.x * blockDim.x + threadIdx.x;
    if (i >= KK*16*2*32) return;
    int l   = i & 31;
    int ost = (i >> 5) & 1;
    int s   = (i >> 6) & 15;
    int tap = i >> 10;
    int o = ost*16 + (l >> 2);
    int c = s*8 + (l & 3);
    float a0 = (o     < 18) ? w[(o*CI + c)*9 + tap]         : 0.f;
    float a1 = (o + 8 < 18) ? w[((o+8)*CI + c)*9 + tap]     : 0.f;
    float a2 = (o     < 18) ? w[(o*CI + c + 4)*9 + tap]     : 0.f;
    float a3 = (o + 8 < 18) ? w[((o+8)*CI + c + 4)*9 + tap] : 0.f;
    uint4 u;
    CVT_TF32(u.x, a0); CVT_TF32(u.y, a1); CVT_TF32(u.z, a2); CVT_TF32(u.w, a3);
    ((uint4*)g_wOffF)[i] = u;
}

// ---------------- K4: fused offset-conv + deformable sampling + TF32 MMA + BN stats ----------------
// block = (h, b): 128 pixels x 128 out channels. 256 threads = 8 warps.
// Phase A (offset conv): halo tile per input row (3 rows, each reused by 3 taps).
// Phase B (main GEMM): wm = wid>>1 (4 M-warps, 32 o), wc = wid&1 (2 N-warps, 64 px).
#define OFF_S    0                       // float [128][CIP] tf32 bits  69632 B
#define OFF_OFF  69632                   // float [18][128] offsets      9216 B
#define SMEM_K4  (OFF_OFF + 9216)
// Phase A scratch: 130*CIP floats = 70720 B, overlapping sS+sOff (written after last use)

__global__ __launch_bounds__(256, 2) void k_main(const float* __restrict__ b_off) {
    extern __shared__ __align__(16) char smem[];
    float* sS   = (float*)(smem + OFF_S);
    float* sOff = (float*)(smem + OFF_OFF);
    float* sX   = (float*)smem;           // Phase A halo tile [130 px][CIP]

    const int h   = blockIdx.x;
    const int b   = blockIdx.y;
    const int tid = threadIdx.x;
    const int wid = tid >> 5;
    const int l   = tid & 31;

    // ================= Phase A: offset conv (18 x 128) via mma.sync =================
    {
        const int wo = wid >> 2;          // 0..1 (o-stripe of 16)
        const int wp = wid & 3;           // 0..3 (32-px group)
        float accO[4][4];
#pragma unroll
        for (int t = 0; t < 4; t++)
#pragma unroll
            for (int j = 0; j < 4; j++) accO[t][j] = 0.f;

        const float* bBaseO = sX + (wp*32 + (l >> 2))*CIP + (l & 3)*2;

        for (int r = 0; r < 3; r++) {
            if (r) __syncthreads();
            const int yy = h - 1 + r;
            const bool yok = (yy >= 0 && yy < Hn);
            // copy halo row (130 px incl. borders), tf32-convert, zero-pad
            for (int i = tid; i < 130*32; i += 256) {
                int p = i >> 5, q = i & 31;
                int sx = p - 1;
                uint4 u = make_uint4(0u, 0u, 0u, 0u);
                if (yok && sx >= 0 && sx < Wn) {
                    float4 v = *(const float4*)(g_xT + (size_t)((b*HW + yy*Wn + sx)*CI) + q*4);
                    CVT_TF32(u.x, v.x); CVT_TF32(u.y, v.y);
                    CVT_TF32(u.z, v.z); CVT_TF32(u.w, v.w);
                }
                *(uint4*)(sX + p*CIP + q*4) = u;
            }
            __syncthreads();
#pragma unroll
            for (int kx = 0; kx < 3; kx++) {
                int k = 3*r + kx;
                const uint4* aBase = (const uint4*)g_wOffF + ((k*16)*2 + wo)*32 + l;
                const float* bShift = bBaseO + kx*CIP;
#pragma unroll 2
                for (int s = 0; s < 16; s++) {
                    uint4 aF = aBase[s*64];
                    const float* bp = bShift + s*8;
#pragma unroll
                    for (int t = 0; t < 4; t++) {
                        uint2 bv = *(const uint2*)(bp + t*8*CIP);
                        mma_tf32(accO[t], aF, bv.x, bv.y);
                    }
                }
            }
        }
        __syncthreads();   // all scratch reads done before sOff overwrite

        // write offsets (+bias) to sOff[channel][px]
        int o0  = wo*16 + (l >> 2);
        int px0 = wp*32 + 2*(l & 3);
        float bo0 = (o0     < 18) ? b_off[o0]     : 0.f;
        float bo1 = (o0 + 8 < 18) ? b_off[o0 + 8] : 0.f;
#pragma unroll
        for (int t = 0; t < 4; t++) {
            int px = px0 + t*8;
            if (o0 < 18) {
                sOff[o0*128 + px]     = accO[t][0] + bo0;
                sOff[o0*128 + px + 1] = accO[t][1] + bo0;
            }
            if (o0 + 8 < 18) {
                sOff[(o0 + 8)*128 + px]     = accO[t][2] + bo1;
                sOff[(o0 + 8)*128 + px + 1] = accO[t][3] + bo1;
            }
        }
    }
    __syncthreads();

    // ================= Phase B: deformable sampling + main GEMM =================
    const int wm  = wid >> 1;
    const int wc  = wid & 1;

    float acc[2][8][4];
#pragma unroll
    for (int st = 0; st < 2; st++)
#pragma unroll
        for (int t = 0; t < 8; t++)
#pragma unroll
            for (int j = 0; j < 4; j++) acc[st][t][j] = 0.f;

    const int spix = tid >> 3;            // sampler: pixel 0..31 (per pass)
    const int sc   = (tid & 7) * 4;       // sampler: channel-position quad base

    const float* bBase = sS + (wc*64 + (l >> 2))*CIP + (l & 3)*2;

    for (int k = 0; k < KK; k++) {
        if (k) __syncthreads();           // protect sS from previous tap's readers
        const int ky = k / 3, kx = k % 3;
        const float* dyp = sOff + (2*k)*128;
        const float* dxp = sOff + (2*k + 1)*128;
#pragma unroll
        for (int pass = 0; pass < 4; pass++) {
            int px = pass*32 + spix;
            float dy = dyp[px];
            float dx = dxp[px];
            float ys = (float)(h - 1 + ky) + dy;
            float xs = (float)(px - 1 + kx) + dx;
            float y0f = floorf(ys), x0f = floorf(xs);
            float wy = ys - y0f, wx = xs - x0f;
            int y0 = (int)y0f, x0 = (int)x0f;
            int y1 = y0 + 1, x1 = x0 + 1;
            float vy0 = (y0 >= 0 && y0 < Hn) ? 1.f : 0.f;
            float vy1 = (y1 >= 0 && y1 < Hn) ? 1.f : 0.f;
            float vx0 = (x0 >= 0 && x0 < Wn) ? 1.f : 0.f;
            float vx1 = (x1 >= 0 && x1 < Wn) ? 1.f : 0.f;
            int y0c = min(max(y0, 0), Hn-1), y1c = min(max(y1, 0), Hn-1);
            int x0c = min(max(x0, 0), Wn-1), x1c = min(max(x1, 0), Wn-1);
            int base = b * HW;
            int i0 = (base + y0c*Wn + x0c)*CI;
            int i1 = (base + y0c*Wn + x1c)*CI;
            int i2 = (base + y1c*Wn + x0c)*CI;
            int i3 = (base + y1c*Wn + x1c)*CI;
            float w00 = (1.f - wy)*(1.f - wx)*vy0*vx0;
            float w01 = (1.f - wy)*wx       *vy0*vx1;
            float w10 = wy       *(1.f - wx)*vy1*vx0;
            float w11 = wy       *wx        *vy1*vx1;
#pragma unroll
            for (int cc = 0; cc < CI; cc += 32) {
                int c = cc + sc;
                float4 p0 = *(const float4*)(g_xT + i0 + c);
                float4 p1 = *(const float4*)(g_xT + i1 + c);
                float4 p2 = *(const float4*)(g_xT + i2 + c);
                float4 p3 = *(const float4*)(g_xT + i3 + c);
                float4 v;
                v.x = w00*p0.x + w01*p1.x + w10*p2.x + w11*p3.x;
                v.y = w00*p0.y + w01*p1.y + w10*p2.y + w11*p3.y;
                v.z = w00*p0.z + w01*p1.z + w10*p2.z + w11*p3.z;
                v.w = w00*p0.w + w01*p1.w + w10*p2.w + w11*p3.w;
                uint4 u;
                CVT_TF32(u.x, v.x); CVT_TF32(u.y, v.y);
                CVT_TF32(u.z, v.z); CVT_TF32(u.w, v.w);
                *(uint4*)(sS + px*CIP + c) = u;
            }
        }
        __syncthreads();

        // --- GEMM: 16 K=8 steps; per step 2 A-frag LDG.128 + 8 B LDS.64 ---
        const uint4* aBase = (const uint4*)g_wF + ((k*16)*8 + 2*wm)*32 + l;
#pragma unroll 2
        for (int s = 0; s < 16; s++) {
            uint4 aF0 = aBase[s*256];          // ostripe 2*wm
            uint4 aF1 = aBase[s*256 + 32];     // ostripe 2*wm + 1
            const float* bp = bBase + s*8;
#pragma unroll
            for (int t = 0; t < 8; t++) {
                uint2 bv = *(const uint2*)(bp + t*8*CIP);
                mma_tf32(acc[0][t], aF0, bv.x, bv.y);
                mma_tf32(acc[1][t], aF1, bv.x, bv.y);
            }
        }
    }

    // --- epilogue: D[o][pix] fragments -> g_conv (NCHW) ---
#pragma unroll
    for (int st = 0; st < 2; st++) {
        int o = 32*wm + st*16 + (l >> 2);
#pragma unroll
        for (int t = 0; t < 8; t++) {
            int px = wc*64 + t*8 + 2*(l & 3);
            float* d = g_conv + ((size_t)(b*CO + o)*Hn + h)*Wn + px;
            *(float2*)d          = make_float2(acc[st][t][0], acc[st][t][1]);
            *(float2*)(d + 8*HW) = make_float2(acc[st][t][2], acc[st][t][3]);
        }
    }

    // --- fused BN stats: quad-reduce, atomic ---
    {
        float s[4] = {0.f, 0.f, 0.f, 0.f};
        float q[4] = {0.f, 0.f, 0.f, 0.f};
#pragma unroll
        for (int st = 0; st < 2; st++)
#pragma unroll
            for (int t = 0; t < 8; t++) {
                float a0 = acc[st][t][0], a1 = acc[st][t][1];
                float a2 = acc[st][t][2], a3 = acc[st][t][3];
                s[2*st]   += a0 + a1;  q[2*st]   += a0*a0 + a1*a1;
                s[2*st+1] += a2 + a3;  q[2*st+1] += a2*a2 + a3*a3;
            }
#pragma unroll
        for (int d = 1; d < 4; d <<= 1)
#pragma unroll
            for (int j = 0; j < 4; j++) {
                s[j] += __shfl_xor_sync(0xffffffffu, s[j], d);
                q[j] += __shfl_xor_sync(0xffffffffu, q[j], d);
            }
        if ((l & 3) == 0) {
            int o0 = 32*wm + (l >> 2);
#pragma unroll
            for (int j = 0; j < 4; j++) {
                int o = o0 + 8*j;
                atomicAdd(&g_stat[o], s[j]);
                atomicAdd(&g_stat[CO + o], q[j]);
            }
        }
    }
}

// ---------------- K5: BN finalize (tiny) ----------------
__global__ void k_bn_finalize(const float* __restrict__ gamma,
                              const float* __restrict__ beta) {
    int o = threadIdx.x;
    float inv_n = 1.f / (float)(Bn*HW);
    float mean = g_stat[o] * inv_n;
    float var  = g_stat[CO + o] * inv_n - mean*mean;
    float r = rsqrtf(var + 0.001f);
    float sc = gamma[o] * r;
    g_scale[o] = sc;
    g_shift[o] = beta[o] - mean*sc;
}

// ---------------- K6: apply BN + ReLU ----------------
__global__ void k_bn_apply(float* __restrict__ out) {
    int i = blockIdx.x * blockDim.x + threadIdx.x;
    int ch = (i >> 12) & 127;
    float4 v = ((const float4*)g_conv)[i];
    float sc = g_scale[ch], sh = g_shift[ch];
    v.x = fmaxf(fmaf(v.x, sc, sh), 0.f);
    v.y = fmaxf(fmaf(v.y, sc, sh), 0.f);
    v.z = fmaxf(fmaf(v.z, sc, sh), 0.f);
    v.w = fmaxf(fmaf(v.w, sc, sh), 0.f);
    ((float4*)out)[i] = v;
}

// ---------------- launch ----------------
extern "C" void kernel_launch(void* const* d_in, const int* in_sizes, int n_in,
                              void* d_out, int out_size) {
    const float* x     = (const float*)d_in[0];
    const float* w_off = (const float*)d_in[1];
    const float* b_off = (const float*)d_in[2];
    const float* w_dcn = (const float*)d_in[3];
    const float* gamma = (const float*)d_in[4];
    const float* beta  = (const float*)d_in[5];
    float* out = (float*)d_out;

    cudaFuncSetAttribute(k_main, cudaFuncAttributeMaxDynamicSharedMemorySize, SMEM_K4);

    k_transpose_x<<<dim3(Wn/32, CI/32, Bn*Hn), dim3(32, 32)>>>(x);
    k_prep_w<<<(KK*16*8*32 + 255)/256, 256>>>(w_dcn);
    k_prep_woff<<<(KK*16*2*32 + 255)/256, 256>>>(w_off);
    k_main<<<dim3(Hn, Bn), 256, SMEM_K4>>>(b_off);
    k_bn_finalize<<<1, CO>>>(gamma, beta);
    k_bn_apply<<<(Bn*CO*HW/4)/256, 256>>>(out);
}

// round 14
// speedup vs baseline: 2.1551x; 1.5734x over previous
#include <cuda_runtime.h>
#include <cuda_fp16.h>
#include <math.h>
#include <cstdint>

#define Bn 4
#define CI 128
#define CO 128
#define Hn 128
#define Wn 128
#define HW (Hn*Wn)
#define KK 9
#define CIPH 144         // fp16 per pixel row (128 + 16 pad) = 288B = 72 words (≡8 mod 32)

// warp-level tensor core MMA: D(16x8,f32) += A(16x16,f16) * B(16x8,f16)
__device__ __forceinline__ void mma_f16(float* c, const uint4& a, uint32_t b0, uint32_t b1) {
    asm volatile("mma.sync.aligned.m16n8k16.row.col.f32.f16.f16.f32 "
        "{%0,%1,%2,%3}, {%4,%5,%6,%7}, {%8,%9}, {%0,%1,%2,%3};"
        : "+f"(c[0]), "+f"(c[1]), "+f"(c[2]), "+f"(c[3])
        : "r"(a.x), "r"(a.y), "r"(a.z), "r"(a.w), "r"(b0), "r"(b1));
}

// channel c -> storage slot: within each 16-group, slots hold channels
// (0,1),(8,9),(2,3),(10,11),(4,5),(12,13),(6,7),(14,15) so each lane's
// B fragment (k=2j,2j+1,2j+8,2j+9) is one contiguous 8-byte LDS.64.
__device__ __forceinline__ int slot16(int c) {
    return (c & ~15) | (((c >> 1) & 3) << 2) | (((c >> 3) & 1) << 1) | (c & 1);
}

// ---------------- scratch ----------------
__device__ __align__(16) __half g_xTh[Bn*HW*CI];     // x NHWC, fp16, slot-permuted
__device__ uint4 g_wFh[KK*8*8*32];                   // w_dcn A-frags (fp16, k16)
__device__ uint4 g_wOffFh[KK*8*2*32];                // w_off A-frags (fp16, M=32 pad)
__device__ __align__(16) float g_conv[Bn*CO*HW];     // pre-BN output
__device__ float g_stat[2*CO];
__device__ float g_scale[CO];
__device__ float g_shift[CO];

// ---------------- K1: NCHW fp32 -> NHWC fp16 slot-permuted ----------------
__global__ void k_transpose_x(const float* __restrict__ in) {
    __shared__ float t[32][33];
    int wb = blockIdx.x * 32, cb = blockIdx.y * 32;
    int by = blockIdx.z;
    int b = by >> 7, y = by & 127;
    t[threadIdx.y][threadIdx.x] =
        in[((b*CI + cb + threadIdx.y)*Hn + y)*Wn + wb + threadIdx.x];
    __syncthreads();
    int c = cb + threadIdx.x;
    g_xTh[(size_t)(by*Wn + wb + threadIdx.y)*CI + slot16(c)] =
        __float2half(t[threadIdx.x][threadIdx.y]);
}

// ---------------- K2a: w_dcn -> fp16 A-fragment prepack; zero g_stat ----------------
// index: ((tap*8 + s)*8 + ost)*32 + lane; lane l: rows o=ost*16+(l>>2), o+8;
// k-cols c0=s*16+(l&3)*2 (+1, +8, +9). Matrix-k = channel (perm lives in x only).
__global__ void k_prep_w(const float* __restrict__ w) {
    if (blockIdx.x == 0 && threadIdx.x < 2*CO) g_stat[threadIdx.x] = 0.f;
    int i = blockIdx.x * blockDim.x + threadIdx.x;
    if (i >= KK*8*8*32) return;
    int l = i & 31;
    int r = i >> 5;
    int ost = r & 7;  r >>= 3;
    int s = r & 7;
    int tap = r >> 3;
    int o = ost*16 + (l >> 2);
    int c0 = s*16 + (l & 3)*2;
    const float* w0 = w + ((size_t)o*CI)*9 + tap;
    const float* w1 = w + ((size_t)(o+8)*CI)*9 + tap;
    __half2 a0 = __floats2half2_rn(w0[c0*9],     w0[(c0+1)*9]);
    __half2 a1 = __floats2half2_rn(w1[c0*9],     w1[(c0+1)*9]);
    __half2 a2 = __floats2half2_rn(w0[(c0+8)*9], w0[(c0+9)*9]);
    __half2 a3 = __floats2half2_rn(w1[(c0+8)*9], w1[(c0+9)*9]);
    uint4 u;
    u.x = *(uint32_t*)&a0; u.y = *(uint32_t*)&a1;
    u.z = *(uint32_t*)&a2; u.w = *(uint32_t*)&a3;
    g_wFh[i] = u;
}

// ---------------- K2b: w_off -> fp16 A-fragment prepack (18 rows padded to 32) ----------------
// index: ((tap*8 + s)*2 + ost)*32 + lane
__global__ void k_prep_woff(const float* __restrict__ w) {
    int i = blockIdx.x * blockDim.x + threadIdx.x;
    if (i >= KK*8*2*32) return;
    int l   = i & 31;
    int ost = (i >> 5) & 1;
    int s   = (i >> 6) & 7;
    int tap = i >> 9;
    int o = ost*16 + (l >> 2);
    int c0 = s*16 + (l & 3)*2;
    float v00 = 0.f, v01 = 0.f, v08 = 0.f, v09 = 0.f;
    float v10 = 0.f, v11 = 0.f, v18 = 0.f, v19 = 0.f;
    if (o < 18) {
        const float* w0 = w + ((size_t)o*CI)*9 + tap;
        v00 = w0[c0*9]; v01 = w0[(c0+1)*9]; v08 = w0[(c0+8)*9]; v09 = w0[(c0+9)*9];
    }
    if (o + 8 < 18) {
        const float* w1 = w + ((size_t)(o+8)*CI)*9 + tap;
        v10 = w1[c0*9]; v11 = w1[(c0+1)*9]; v18 = w1[(c0+8)*9]; v19 = w1[(c0+9)*9];
    }
    __half2 a0 = __floats2half2_rn(v00, v01);
    __half2 a1 = __floats2half2_rn(v10, v11);
    __half2 a2 = __floats2half2_rn(v08, v09);
    __half2 a3 = __floats2half2_rn(v18, v19);
    uint4 u;
    u.x = *(uint32_t*)&a0; u.y = *(uint32_t*)&a1;
    u.z = *(uint32_t*)&a2; u.w = *(uint32_t*)&a3;
    g_wOffFh[i] = u;
}

// ---------------- K4: fused offset-conv + deformable sampling + f16 MMA + BN stats ----------------
// block = (h, b): 128 pixels x 128 out channels. 256 threads = 8 warps.
#define OFF_S    0                       // __half [128][CIPH]  36864 B
#define OFF_OFF  36864                   // float  [18][128]     9216 B
#define SMEM_K4  (OFF_OFF + 9216)
// Phase A halo tile: __half [130][CIPH] = 37440 B (overlaps sS+sOff; synced before reuse)

__global__ __launch_bounds__(256, 2) void k_main(const float* __restrict__ b_off) {
    extern __shared__ __align__(16) char smem[];
    __half* sS   = (__half*)(smem + OFF_S);
    float*  sOff = (float*)(smem + OFF_OFF);
    __half* sX   = (__half*)smem;         // Phase A halo tile [130][CIPH]

    const int h   = blockIdx.x;
    const int b   = blockIdx.y;
    const int tid = threadIdx.x;
    const int wid = tid >> 5;
    const int l   = tid & 31;

    // ================= Phase A: offset conv (18 x 128) via m16n8k16 =================
    {
        const int wo = wid >> 2;          // 0..1 (o-stripe of 16)
        const int wp = wid & 3;           // 0..3 (32-px group)
        float accO[4][4];
#pragma unroll
        for (int t = 0; t < 4; t++)
#pragma unroll
            for (int j = 0; j < 4; j++) accO[t][j] = 0.f;

        const __half* bBaseO = sX + (wp*32 + (l >> 2))*CIPH + (l & 3)*4;

        for (int r = 0; r < 3; r++) {
            if (r) __syncthreads();
            const int yy = h - 1 + r;
            const bool yok = (yy >= 0 && yy < Hn);
            // copy halo row (130 px), zero-pad borders; pure fp16 copy
            for (int i = tid; i < 130*16; i += 256) {
                int p = i >> 4, q = i & 15;
                int sx = p - 1;
                uint4 u = make_uint4(0u, 0u, 0u, 0u);
                if (yok && sx >= 0 && sx < Wn)
                    u = *(const uint4*)(g_xTh + (size_t)(b*HW + yy*Wn + sx)*CI + q*8);
                *(uint4*)(sX + p*CIPH + q*8) = u;
            }
            __syncthreads();
#pragma unroll
            for (int kx = 0; kx < 3; kx++) {
                int k = 3*r + kx;
                const uint4* aBase = g_wOffFh + ((k*8)*2 + wo)*32 + l;
                const __half* bShift = bBaseO + kx*CIPH;
#pragma unroll
                for (int s = 0; s < 8; s++) {
                    uint4 aF = aBase[s*64];
                    const __half* bp = bShift + s*16;
#pragma unroll
                    for (int t = 0; t < 4; t++) {
                        uint2 bv = *(const uint2*)(bp + t*8*CIPH);
                        mma_f16(accO[t], aF, bv.x, bv.y);
                    }
                }
            }
        }
        __syncthreads();   // all halo reads done before sOff overwrite

        // write offsets (+bias) to sOff[channel][px]
        int o0  = wo*16 + (l >> 2);
        int px0 = wp*32 + 2*(l & 3);
        float bo0 = (o0     < 18) ? b_off[o0]     : 0.f;
        float bo1 = (o0 + 8 < 18) ? b_off[o0 + 8] : 0.f;
#pragma unroll
        for (int t = 0; t < 4; t++) {
            int px = px0 + t*8;
            if (o0 < 18) {
                sOff[o0*128 + px]     = accO[t][0] + bo0;
                sOff[o0*128 + px + 1] = accO[t][1] + bo0;
            }
            if (o0 + 8 < 18) {
                sOff[(o0 + 8)*128 + px]     = accO[t][2] + bo1;
                sOff[(o0 + 8)*128 + px + 1] = accO[t][3] + bo1;
            }
        }
    }
    __syncthreads();

    // ================= Phase B: deformable sampling + main GEMM =================
    const int wm  = wid >> 1;
    const int wc  = wid & 1;

    float acc[2][8][4];
#pragma unroll
    for (int st = 0; st < 2; st++)
#pragma unroll
        for (int t = 0; t < 8; t++)
#pragma unroll
            for (int j = 0; j < 4; j++) acc[st][t][j] = 0.f;

    const int spix  = tid >> 3;           // sampler: pixel 0..31 (per pass)
    const int lane8 = tid & 7;

    const __half* bBase = sS + (wc*64 + (l >> 2))*CIPH + (l & 3)*4;

    for (int k = 0; k < KK; k++) {
        if (k) __syncthreads();           // protect sS from previous tap's readers
        const int ky = k / 3, kx = k % 3;
        const float* dyp = sOff + (2*k)*128;
        const float* dxp = sOff + (2*k + 1)*128;
#pragma unroll
        for (int pass = 0; pass < 4; pass++) {
            int px = pass*32 + spix;
            float dy = dyp[px];
            float dx = dxp[px];
            float ys = (float)(h - 1 + ky) + dy;
            float xs = (float)(px - 1 + kx) + dx;
            float y0f = floorf(ys), x0f = floorf(xs);
            float wy = ys - y0f, wx = xs - x0f;
            int y0 = (int)y0f, x0 = (int)x0f;
            int y1 = y0 + 1, x1 = x0 + 1;
            float vy0 = (y0 >= 0 && y0 < Hn) ? 1.f : 0.f;
            float vy1 = (y1 >= 0 && y1 < Hn) ? 1.f : 0.f;
            float vx0 = (x0 >= 0 && x0 < Wn) ? 1.f : 0.f;
            float vx1 = (x1 >= 0 && x1 < Wn) ? 1.f : 0.f;
            int y0c = min(max(y0, 0), Hn-1), y1c = min(max(y1, 0), Hn-1);
            int x0c = min(max(x0, 0), Wn-1), x1c = min(max(x1, 0), Wn-1);
            int base = b * HW;
            int i0 = (base + y0c*Wn + x0c)*CI;
            int i1 = (base + y0c*Wn + x1c)*CI;
            int i2 = (base + y1c*Wn + x0c)*CI;
            int i3 = (base + y1c*Wn + x1c)*CI;
            float w00 = (1.f - wy)*(1.f - wx)*vy0*vx0;
            float w01 = (1.f - wy)*wx       *vy0*vx1;
            float w10 = wy       *(1.f - wx)*vy1*vx0;
            float w11 = wy       *wx        *vy1*vx1;
#pragma unroll
            for (int cc = 0; cc < CI; cc += 64) {
                int c = cc + lane8*8;     // 8 slots per lane
                uint4 u0 = *(const uint4*)(g_xTh + i0 + c);
                uint4 u1 = *(const uint4*)(g_xTh + i1 + c);
                uint4 u2 = *(const uint4*)(g_xTh + i2 + c);
                uint4 u3 = *(const uint4*)(g_xTh + i3 + c);
                uint4 outv;
#pragma unroll
                for (int j = 0; j < 4; j++) {
                    float2 f0 = __half22float2(((const __half2*)&u0)[j]);
                    float2 f1 = __half22float2(((const __half2*)&u1)[j]);
                    float2 f2 = __half22float2(((const __half2*)&u2)[j]);
                    float2 f3 = __half22float2(((const __half2*)&u3)[j]);
                    float rx = w00*f0.x + w01*f1.x + w10*f2.x + w11*f3.x;
                    float ry = w00*f0.y + w01*f1.y + w10*f2.y + w11*f3.y;
                    __half2 hv = __floats2half2_rn(rx, ry);
                    ((__half2*)&outv)[j] = hv;
                }
                *(uint4*)(sS + px*CIPH + c) = outv;
            }
        }
        __syncthreads();

        // --- GEMM: 8 K=16 steps; per step 2 A-frag LDG.128 + 8 B LDS.64 ---
        const uint4* aBase = g_wFh + ((k*8)*8 + 2*wm)*32 + l;
#pragma unroll
        for (int s = 0; s < 8; s++) {
            uint4 aF0 = aBase[s*256];          // ostripe 2*wm
            uint4 aF1 = aBase[s*256 + 32];     // ostripe 2*wm + 1
            const __half* bp = bBase + s*16;
#pragma unroll
            for (int t = 0; t < 8; t++) {
                uint2 bv = *(const uint2*)(bp + t*8*CIPH);
                mma_f16(acc[0][t], aF0, bv.x, bv.y);
                mma_f16(acc[1][t], aF1, bv.x, bv.y);
            }
        }
    }

    // --- epilogue: D[o][pix] fragments -> g_conv (NCHW) ---
#pragma unroll
    for (int st = 0; st < 2; st++) {
        int o = 32*wm + st*16 + (l >> 2);
#pragma unroll
        for (int t = 0; t < 8; t++) {
            int px = wc*64 + t*8 + 2*(l & 3);
            float* d = g_conv + ((size_t)(b*CO + o)*Hn + h)*Wn + px;
            *(float2*)d          = make_float2(acc[st][t][0], acc[st][t][1]);
            *(float2*)(d + 8*HW) = make_float2(acc[st][t][2], acc[st][t][3]);
        }
    }

    // --- fused BN stats: quad-reduce, atomic ---
    {
        float s[4] = {0.f, 0.f, 0.f, 0.f};
        float q[4] = {0.f, 0.f, 0.f, 0.f};
#pragma unroll
        for (int st = 0; st < 2; st++)
#pragma unroll
            for (int t = 0; t < 8; t++) {
                float a0 = acc[st][t][0], a1 = acc[st][t][1];
                float a2 = acc[st][t][2], a3 = acc[st][t][3];
                s[2*st]   += a0 + a1;  q[2*st]   += a0*a0 + a1*a1;
                s[2*st+1] += a2 + a3;  q[2*st+1] += a2*a2 + a3*a3;
            }
#pragma unroll
        for (int d = 1; d < 4; d <<= 1)
#pragma unroll
            for (int j = 0; j < 4; j++) {
                s[j] += __shfl_xor_sync(0xffffffffu, s[j], d);
                q[j] += __shfl_xor_sync(0xffffffffu, q[j], d);
            }
        if ((l & 3) == 0) {
            int o0 = 32*wm + (l >> 2);
#pragma unroll
            for (int j = 0; j < 4; j++) {
                int o = o0 + 8*j;
                atomicAdd(&g_stat[o], s[j]);
                atomicAdd(&g_stat[CO + o], q[j]);
            }
        }
    }
}

// ---------------- K5: BN finalize (tiny) ----------------
__global__ void k_bn_finalize(const float* __restrict__ gamma,
                              const float* __restrict__ beta) {
    int o = threadIdx.x;
    float inv_n = 1.f / (float)(Bn*HW);
    float mean = g_stat[o] * inv_n;
    float var  = g_stat[CO + o] * inv_n - mean*mean;
    float r = rsqrtf(var + 0.001f);
    float sc = gamma[o] * r;
    g_scale[o] = sc;
    g_shift[o] = beta[o] - mean*sc;
}

// ---------------- K6: apply BN + ReLU ----------------
__global__ void k_bn_apply(float* __restrict__ out) {
    int i = blockIdx.x * blockDim.x + threadIdx.x;
    int ch = (i >> 12) & 127;
    float4 v = ((const float4*)g_conv)[i];
    float sc = g_scale[ch], sh = g_shift[ch];
    v.x = fmaxf(fmaf(v.x, sc, sh), 0.f);
    v.y = fmaxf(fmaf(v.y, sc, sh), 0.f);
    v.z = fmaxf(fmaf(v.z, sc, sh), 0.f);
    v.w = fmaxf(fmaf(v.w, sc, sh), 0.f);
    ((float4*)out)[i] = v;
}

// ---------------- launch ----------------
extern "C" void kernel_launch(void* const* d_in, const int* in_sizes, int n_in,
                              void* d_out, int out_size) {
    const float* x     = (const float*)d_in[0];
    const float* w_off = (const float*)d_in[1];
    const float* b_off = (const float*)d_in[2];
    const float* w_dcn = (const float*)d_in[3];
    const float* gamma = (const float*)d_in[4];
    const float* beta  = (const float*)d_in[5];
    float* out = (float*)d_out;

    cudaFuncSetAttribute(k_main, cudaFuncAttributeMaxDynamicSharedMemorySize, SMEM_K4);

    k_transpose_x<<<dim3(Wn/32, CI/32, Bn*Hn), dim3(32, 32)>>>(x);
    k_prep_w<<<(KK*8*8*32 + 255)/256, 256>>>(w_dcn);
    k_prep_woff<<<(KK*8*2*32 + 255)/256, 256>>>(w_off);
    k_main<<<dim3(Hn, Bn), 256, SMEM_K4>>>(b_off);
    k_bn_finalize<<<1, CO>>>(gamma, beta);
    k_bn_apply<<<(Bn*CO*HW/4)/256, 256>>>(out);
}

// round 15
// speedup vs baseline: 2.1733x; 1.0085x over previous
#include <cuda_runtime.h>
#include <cuda_fp16.h>
#include <math.h>
#include <cstdint>

#define Bn 4
#define CI 128
#define CO 128
#define Hn 128
#define Wn 128
#define HW (Hn*Wn)
#define KK 9
#define CIPH 144         // fp16 per pixel row (128 + 16 pad) = 288B = 72 words (≡8 mod 32)
#define BUFH (130*CIPH)  // one buffer, halfs (130 rows: Phase A halo needs 130)

// warp-level tensor core MMA: D(16x8,f32) += A(16x16,f16) * B(16x8,f16)
__device__ __forceinline__ void mma_f16(float* c, const uint4& a, uint32_t b0, uint32_t b1) {
    asm volatile("mma.sync.aligned.m16n8k16.row.col.f32.f16.f16.f32 "
        "{%0,%1,%2,%3}, {%4,%5,%6,%7}, {%8,%9}, {%0,%1,%2,%3};"
        : "+f"(c[0]), "+f"(c[1]), "+f"(c[2]), "+f"(c[3])
        : "r"(a.x), "r"(a.y), "r"(a.z), "r"(a.w), "r"(b0), "r"(b1));
}

// channel c -> storage slot: within each 16-group, slots hold channels
// (0,1),(8,9),(2,3),(10,11),(4,5),(12,13),(6,7),(14,15) so each lane's
// B fragment (k=2j,2j+1,2j+8,2j+9) is one contiguous 8-byte LDS.64.
__device__ __forceinline__ int slot16(int c) {
    return (c & ~15) | (((c >> 1) & 3) << 2) | (((c >> 3) & 1) << 1) | (c & 1);
}

// ---------------- scratch ----------------
__device__ __align__(16) __half g_xTh[Bn*HW*CI];     // x NHWC, fp16, slot-permuted
__device__ uint4 g_wFh[KK*8*8*32];                   // w_dcn A-frags (fp16, k16)
__device__ uint4 g_wOffFh[KK*8*2*32];                // w_off A-frags (fp16, M=32 pad)
__device__ __align__(16) float g_conv[Bn*CO*HW];     // pre-BN output
__device__ float g_stat[2*CO];
__device__ float g_scale[CO];
__device__ float g_shift[CO];

// ---------------- K1: NCHW fp32 -> NHWC fp16 slot-permuted ----------------
__global__ void k_transpose_x(const float* __restrict__ in) {
    __shared__ float t[32][33];
    int wb = blockIdx.x * 32, cb = blockIdx.y * 32;
    int by = blockIdx.z;
    int b = by >> 7, y = by & 127;
    t[threadIdx.y][threadIdx.x] =
        in[((b*CI + cb + threadIdx.y)*Hn + y)*Wn + wb + threadIdx.x];
    __syncthreads();
    int c = cb + threadIdx.x;
    g_xTh[(size_t)(by*Wn + wb + threadIdx.y)*CI + slot16(c)] =
        __float2half(t[threadIdx.x][threadIdx.y]);
}

// ---------------- K2a: w_dcn -> fp16 A-fragment prepack; zero g_stat ----------------
__global__ void k_prep_w(const float* __restrict__ w) {
    if (blockIdx.x == 0 && threadIdx.x < 2*CO) g_stat[threadIdx.x] = 0.f;
    int i = blockIdx.x * blockDim.x + threadIdx.x;
    if (i >= KK*8*8*32) return;
    int l = i & 31;
    int r = i >> 5;
    int ost = r & 7;  r >>= 3;
    int s = r & 7;
    int tap = r >> 3;
    int o = ost*16 + (l >> 2);
    int c0 = s*16 + (l & 3)*2;
    const float* w0 = w + ((size_t)o*CI)*9 + tap;
    const float* w1 = w + ((size_t)(o+8)*CI)*9 + tap;
    __half2 a0 = __floats2half2_rn(w0[c0*9],     w0[(c0+1)*9]);
    __half2 a1 = __floats2half2_rn(w1[c0*9],     w1[(c0+1)*9]);
    __half2 a2 = __floats2half2_rn(w0[(c0+8)*9], w0[(c0+9)*9]);
    __half2 a3 = __floats2half2_rn(w1[(c0+8)*9], w1[(c0+9)*9]);
    uint4 u;
    u.x = *(uint32_t*)&a0; u.y = *(uint32_t*)&a1;
    u.z = *(uint32_t*)&a2; u.w = *(uint32_t*)&a3;
    g_wFh[i] = u;
}

// ---------------- K2b: w_off -> fp16 A-fragment prepack (18 rows padded to 32) ----------------
__global__ void k_prep_woff(const float* __restrict__ w) {
    int i = blockIdx.x * blockDim.x + threadIdx.x;
    if (i >= KK*8*2*32) return;
    int l   = i & 31;
    int ost = (i >> 5) & 1;
    int s   = (i >> 6) & 7;
    int tap = i >> 9;
    int o = ost*16 + (l >> 2);
    int c0 = s*16 + (l & 3)*2;
    float v00 = 0.f, v01 = 0.f, v08 = 0.f, v09 = 0.f;
    float v10 = 0.f, v11 = 0.f, v18 = 0.f, v19 = 0.f;
    if (o < 18) {
        const float* w0 = w + ((size_t)o*CI)*9 + tap;
        v00 = w0[c0*9]; v01 = w0[(c0+1)*9]; v08 = w0[(c0+8)*9]; v09 = w0[(c0+9)*9];
    }
    if (o + 8 < 18) {
        const float* w1 = w + ((size_t)(o+8)*CI)*9 + tap;
        v10 = w1[c0*9]; v11 = w1[(c0+1)*9]; v18 = w1[(c0+8)*9]; v19 = w1[(c0+9)*9];
    }
    __half2 a0 = __floats2half2_rn(v00, v01);
    __half2 a1 = __floats2half2_rn(v10, v11);
    __half2 a2 = __floats2half2_rn(v08, v09);
    __half2 a3 = __floats2half2_rn(v18, v19);
    uint4 u;
    u.x = *(uint32_t*)&a0; u.y = *(uint32_t*)&a1;
    u.z = *(uint32_t*)&a2; u.w = *(uint32_t*)&a3;
    g_wOffFh[i] = u;
}

// ---------------- K4: fused offset-conv + deformable sampling + f16 MMA + BN stats ----------------
// block = (h, b): 128 pixels x 128 out channels. 256 threads = 8 warps.
// Double-buffered tile -> ONE barrier per row/tap; producers of buf[i] are
// protected from its previous readers by the preceding iteration's barrier.
#define OFF_OFF  (2*BUFH*2)              // 2 buffers of BUFH halfs -> byte offset 74880
#define SMEM_K4  (OFF_OFF + 9216)        // + float[18][128] offsets

__global__ __launch_bounds__(256, 2) void k_main(const float* __restrict__ b_off) {
    extern __shared__ __align__(16) char smem[];
    __half* buf0 = (__half*)smem;
    __half* buf1 = buf0 + BUFH;
    float*  sOff = (float*)(smem + OFF_OFF);

    const int h   = blockIdx.x;
    const int b   = blockIdx.y;
    const int tid = threadIdx.x;
    const int wid = tid >> 5;
    const int l   = tid & 31;

    // ================= Phase A: offset conv (18 x 128) via m16n8k16 =================
    {
        const int wo = wid >> 2;          // 0..1 (o-stripe of 16)
        const int wp = wid & 3;           // 0..3 (32-px group)
        float accO[4][4];
#pragma unroll
        for (int t = 0; t < 4; t++)
#pragma unroll
            for (int j = 0; j < 4; j++) accO[t][j] = 0.f;

        for (int r = 0; r < 3; r++) {
            __half* halo = (r & 1) ? buf1 : buf0;
            const int yy = h - 1 + r;
            const bool yok = (yy >= 0 && yy < Hn);
            // copy halo row (130 px), zero-pad borders; pure fp16 copy
            for (int i = tid; i < 130*16; i += 256) {
                int p = i >> 4, q = i & 15;
                int sx = p - 1;
                uint4 u = make_uint4(0u, 0u, 0u, 0u);
                if (yok && sx >= 0 && sx < Wn)
                    u = *(const uint4*)(g_xTh + (size_t)(b*HW + yy*Wn + sx)*CI + q*8);
                *(uint4*)(halo + p*CIPH + q*8) = u;
            }
            __syncthreads();
            const __half* bBaseO = halo + (wp*32 + (l >> 2))*CIPH + (l & 3)*4;
#pragma unroll
            for (int kx = 0; kx < 3; kx++) {
                int k = 3*r + kx;
                const uint4* aBase = g_wOffFh + ((k*8)*2 + wo)*32 + l;
                const __half* bShift = bBaseO + kx*CIPH;
#pragma unroll
                for (int s = 0; s < 8; s++) {
                    uint4 aF = aBase[s*64];
                    const __half* bp = bShift + s*16;
#pragma unroll
                    for (int t = 0; t < 4; t++) {
                        uint2 bv = *(const uint2*)(bp + t*8*CIPH);
                        mma_f16(accO[t], aF, bv.x, bv.y);
                    }
                }
            }
        }

        // write offsets (+bias) to sOff[channel][px] (separate region, no halo overlap)
        int o0  = wo*16 + (l >> 2);
        int px0 = wp*32 + 2*(l & 3);
        float bo0 = (o0     < 18) ? b_off[o0]     : 0.f;
        float bo1 = (o0 + 8 < 18) ? b_off[o0 + 8] : 0.f;
#pragma unroll
        for (int t = 0; t < 4; t++) {
            int px = px0 + t*8;
            if (o0 < 18) {
                sOff[o0*128 + px]     = accO[t][0] + bo0;
                sOff[o0*128 + px + 1] = accO[t][1] + bo0;
            }
            if (o0 + 8 < 18) {
                sOff[(o0 + 8)*128 + px]     = accO[t][2] + bo1;
                sOff[(o0 + 8)*128 + px + 1] = accO[t][3] + bo1;
            }
        }
    }
    __syncthreads();   // sOff ready; all Phase-A buffer reads complete

    // ================= Phase B: deformable sampling + main GEMM =================
    const int wm  = wid >> 1;
    const int wc  = wid & 1;

    float acc[2][8][4];
#pragma unroll
    for (int st = 0; st < 2; st++)
#pragma unroll
        for (int t = 0; t < 8; t++)
#pragma unroll
            for (int j = 0; j < 4; j++) acc[st][t][j] = 0.f;

    const int spix  = tid >> 3;           // sampler: pixel 0..31 (per pass)
    const int lane8 = tid & 7;

    for (int k = 0; k < KK; k++) {
        __half* sS = (k & 1) ? buf1 : buf0;
        const int ky = k / 3, kx = k % 3;
        const float* dyp = sOff + (2*k)*128;
        const float* dxp = sOff + (2*k + 1)*128;
#pragma unroll
        for (int pass = 0; pass < 4; pass++) {
            int px = pass*32 + spix;
            float dy = dyp[px];
            float dx = dxp[px];
            float ys = (float)(h - 1 + ky) + dy;
            float xs = (float)(px - 1 + kx) + dx;
            float y0f = floorf(ys), x0f = floorf(xs);
            float wy = ys - y0f, wx = xs - x0f;
            int y0 = (int)y0f, x0 = (int)x0f;
            int y1 = y0 + 1, x1 = x0 + 1;
            float vy0 = (y0 >= 0 && y0 < Hn) ? 1.f : 0.f;
            float vy1 = (y1 >= 0 && y1 < Hn) ? 1.f : 0.f;
            float vx0 = (x0 >= 0 && x0 < Wn) ? 1.f : 0.f;
            float vx1 = (x1 >= 0 && x1 < Wn) ? 1.f : 0.f;
            int y0c = min(max(y0, 0), Hn-1), y1c = min(max(y1, 0), Hn-1);
            int x0c = min(max(x0, 0), Wn-1), x1c = min(max(x1, 0), Wn-1);
            int base = b * HW;
            int i0 = (base + y0c*Wn + x0c)*CI;
            int i1 = (base + y0c*Wn + x1c)*CI;
            int i2 = (base + y1c*Wn + x0c)*CI;
            int i3 = (base + y1c*Wn + x1c)*CI;
            float w00 = (1.f - wy)*(1.f - wx)*vy0*vx0;
            float w01 = (1.f - wy)*wx       *vy0*vx1;
            float w10 = wy       *(1.f - wx)*vy1*vx0;
            float w11 = wy       *wx        *vy1*vx1;
#pragma unroll
            for (int cc = 0; cc < CI; cc += 64) {
                int c = cc + lane8*8;     // 8 slots per lane
                uint4 u0 = *(const uint4*)(g_xTh + i0 + c);
                uint4 u1 = *(const uint4*)(g_xTh + i1 + c);
                uint4 u2 = *(const uint4*)(g_xTh + i2 + c);
                uint4 u3 = *(const uint4*)(g_xTh + i3 + c);
                uint4 outv;
#pragma unroll
                for (int j = 0; j < 4; j++) {
                    float2 f0 = __half22float2(((const __half2*)&u0)[j]);
                    float2 f1 = __half22float2(((const __half2*)&u1)[j]);
                    float2 f2 = __half22float2(((const __half2*)&u2)[j]);
                    float2 f3 = __half22float2(((const __half2*)&u3)[j]);
                    float rx = w00*f0.x + w01*f1.x + w10*f2.x + w11*f3.x;
                    float ry = w00*f0.y + w01*f1.y + w10*f2.y + w11*f3.y;
                    __half2 hv = __floats2half2_rn(rx, ry);
                    ((__half2*)&outv)[j] = hv;
                }
                *(uint4*)(sS + px*CIPH + c) = outv;
            }
        }
        __syncthreads();   // the ONLY barrier per tap

        // --- GEMM: 8 K=16 steps; per step 2 A-frag LDG.128 + 8 B LDS.64 ---
        const __half* bBase = sS + (wc*64 + (l >> 2))*CIPH + (l & 3)*4;
        const uint4* aBase = g_wFh + ((k*8)*8 + 2*wm)*32 + l;
#pragma unroll
        for (int s = 0; s < 8; s++) {
            uint4 aF0 = aBase[s*256];          // ostripe 2*wm
            uint4 aF1 = aBase[s*256 + 32];     // ostripe 2*wm + 1
            const __half* bp = bBase + s*16;
#pragma unroll
            for (int t = 0; t < 8; t++) {
                uint2 bv = *(const uint2*)(bp + t*8*CIPH);
                mma_f16(acc[0][t], aF0, bv.x, bv.y);
                mma_f16(acc[1][t], aF1, bv.x, bv.y);
            }
        }
    }

    // --- epilogue: D[o][pix] fragments -> g_conv (NCHW) ---
#pragma unroll
    for (int st = 0; st < 2; st++) {
        int o = 32*wm + st*16 + (l >> 2);
#pragma unroll
        for (int t = 0; t < 8; t++) {
            int px = wc*64 + t*8 + 2*(l & 3);
            float* d = g_conv + ((size_t)(b*CO + o)*Hn + h)*Wn + px;
            *(float2*)d          = make_float2(acc[st][t][0], acc[st][t][1]);
            *(float2*)(d + 8*HW) = make_float2(acc[st][t][2], acc[st][t][3]);
        }
    }

    // --- fused BN stats: quad-reduce, atomic ---
    {
        float s[4] = {0.f, 0.f, 0.f, 0.f};
        float q[4] = {0.f, 0.f, 0.f, 0.f};
#pragma unroll
        for (int st = 0; st < 2; st++)
#pragma unroll
            for (int t = 0; t < 8; t++) {
                float a0 = acc[st][t][0], a1 = acc[st][t][1];
                float a2 = acc[st][t][2], a3 = acc[st][t][3];
                s[2*st]   += a0 + a1;  q[2*st]   += a0*a0 + a1*a1;
                s[2*st+1] += a2 + a3;  q[2*st+1] += a2*a2 + a3*a3;
            }
#pragma unroll
        for (int d = 1; d < 4; d <<= 1)
#pragma unroll
            for (int j = 0; j < 4; j++) {
                s[j] += __shfl_xor_sync(0xffffffffu, s[j], d);
                q[j] += __shfl_xor_sync(0xffffffffu, q[j], d);
            }
        if ((l & 3) == 0) {
            int o0 = 32*wm + (l >> 2);
#pragma unroll
            for (int j = 0; j < 4; j++) {
                int o = o0 + 8*j;
                atomicAdd(&g_stat[o], s[j]);
                atomicAdd(&g_stat[CO + o], q[j]);
            }
        }
    }
}

// ---------------- K5: BN finalize (tiny) ----------------
__global__ void k_bn_finalize(const float* __restrict__ gamma,
                              const float* __restrict__ beta) {
    int o = threadIdx.x;
    float inv_n = 1.f / (float)(Bn*HW);
    float mean = g_stat[o] * inv_n;
    float var  = g_stat[CO + o] * inv_n - mean*mean;
    float r = rsqrtf(var + 0.001f);
    float sc = gamma[o] * r;
    g_scale[o] = sc;
    g_shift[o] = beta[o] - mean*sc;
}

// ---------------- K6: apply BN + ReLU ----------------
__global__ void k_bn_apply(float* __restrict__ out) {
    int i = blockIdx.x * blockDim.x + threadIdx.x;
    int ch = (i >> 12) & 127;
    float4 v = ((const float4*)g_conv)[i];
    float sc = g_scale[ch], sh = g_shift[ch];
    v.x = fmaxf(fmaf(v.x, sc, sh), 0.f);
    v.y = fmaxf(fmaf(v.y, sc, sh), 0.f);
    v.z = fmaxf(fmaf(v.z, sc, sh), 0.f);
    v.w = fmaxf(fmaf(v.w, sc, sh), 0.f);
    ((float4*)out)[i] = v;
}

// ---------------- launch ----------------
extern "C" void kernel_launch(void* const* d_in, const int* in_sizes, int n_in,
                              void* d_out, int out_size) {
    const float* x     = (const float*)d_in[0];
    const float* w_off = (const float*)d_in[1];
    const float* b_off = (const float*)d_in[2];
    const float* w_dcn = (const float*)d_in[3];
    const float* gamma = (const float*)d_in[4];
    const float* beta  = (const float*)d_in[5];
    float* out = (float*)d_out;

    cudaFuncSetAttribute(k_main, cudaFuncAttributeMaxDynamicSharedMemorySize, SMEM_K4);

    k_transpose_x<<<dim3(Wn/32, CI/32, Bn*Hn), dim3(32, 32)>>>(x);
    k_prep_w<<<(KK*8*8*32 + 255)/256, 256>>>(w_dcn);
    k_prep_woff<<<(KK*8*2*32 + 255)/256, 256>>>(w_off);
    k_main<<<dim3(Hn, Bn), 256, SMEM_K4>>>(b_off);
    k_bn_finalize<<<1, CO>>>(gamma, beta);
    k_bn_apply<<<(Bn*CO*HW/4)/256, 256>>>(out);
}

// round 16
// speedup vs baseline: 2.3569x; 1.0845x over previous
#include <cuda_runtime.h>
#include <cuda_fp16.h>
#include <math.h>
#include <cstdint>

#define Bn 4
#define CI 128
#define CO 128
#define Hn 128
#define Wn 128
#define HW (Hn*Wn)
#define KK 9
#define CIPH 144         // fp16 per pixel row (128 + 16 pad) = 288B = 72 words (≡8 mod 32)
#define BUFH (130*CIPH)  // one buffer, halfs (130 rows: Phase A halo needs 130)

// warp-level tensor core MMA: D(16x8,f32) += A(16x16,f16) * B(16x8,f16)
__device__ __forceinline__ void mma_f16(float* c, const uint4& a, uint32_t b0, uint32_t b1) {
    asm volatile("mma.sync.aligned.m16n8k16.row.col.f32.f16.f16.f32 "
        "{%0,%1,%2,%3}, {%4,%5,%6,%7}, {%8,%9}, {%0,%1,%2,%3};"
        : "+f"(c[0]), "+f"(c[1]), "+f"(c[2]), "+f"(c[3])
        : "r"(a.x), "r"(a.y), "r"(a.z), "r"(a.w), "r"(b0), "r"(b1));
}

// channel c -> storage slot: within each 16-group, slots hold channels
// (0,1),(8,9),(2,3),(10,11),(4,5),(12,13),(6,7),(14,15) so each lane's
// B fragment (k=2j,2j+1,2j+8,2j+9) is one contiguous 8-byte LDS.64.
__device__ __forceinline__ int slot16(int c) {
    return (c & ~15) | (((c >> 1) & 3) << 2) | (((c >> 3) & 1) << 1) | (c & 1);
}

// ---------------- scratch ----------------
__device__ __align__(16) __half g_xTh[Bn*HW*CI];     // x NHWC, fp16, slot-permuted
__device__ uint4 g_wFh[KK*8*8*32];                   // w_dcn A-frags (fp16, k16)
__device__ uint4 g_wOffFh[KK*8*2*32];                // w_off A-frags (fp16, M=32 pad)
__device__ __align__(16) __half g_convh[Bn*CO*HW];   // pre-BN output (fp16)
__device__ float g_stat[2*CO];
__device__ float g_scale[CO];
__device__ float g_shift[CO];

// ---------------- K1: NCHW fp32 -> NHWC fp16 slot-permuted ----------------
__global__ void k_transpose_x(const float* __restrict__ in) {
    __shared__ float t[32][33];
    int wb = blockIdx.x * 32, cb = blockIdx.y * 32;
    int by = blockIdx.z;
    int b = by >> 7, y = by & 127;
    t[threadIdx.y][threadIdx.x] =
        in[((b*CI + cb + threadIdx.y)*Hn + y)*Wn + wb + threadIdx.x];
    __syncthreads();
    int c = cb + threadIdx.x;
    g_xTh[(size_t)(by*Wn + wb + threadIdx.y)*CI + slot16(c)] =
        __float2half(t[threadIdx.x][threadIdx.y]);
}

// ---------------- K2a: w_dcn -> fp16 A-fragment prepack; zero g_stat ----------------
__global__ void k_prep_w(const float* __restrict__ w) {
    if (blockIdx.x == 0 && threadIdx.x < 2*CO) g_stat[threadIdx.x] = 0.f;
    int i = blockIdx.x * blockDim.x + threadIdx.x;
    if (i >= KK*8*8*32) return;
    int l = i & 31;
    int r = i >> 5;
    int ost = r & 7;  r >>= 3;
    int s = r & 7;
    int tap = r >> 3;
    int o = ost*16 + (l >> 2);
    int c0 = s*16 + (l & 3)*2;
    const float* w0 = w + ((size_t)o*CI)*9 + tap;
    const float* w1 = w + ((size_t)(o+8)*CI)*9 + tap;
    __half2 a0 = __floats2half2_rn(w0[c0*9],     w0[(c0+1)*9]);
    __half2 a1 = __floats2half2_rn(w1[c0*9],     w1[(c0+1)*9]);
    __half2 a2 = __floats2half2_rn(w0[(c0+8)*9], w0[(c0+9)*9]);
    __half2 a3 = __floats2half2_rn(w1[(c0+8)*9], w1[(c0+9)*9]);
    uint4 u;
    u.x = *(uint32_t*)&a0; u.y = *(uint32_t*)&a1;
    u.z = *(uint32_t*)&a2; u.w = *(uint32_t*)&a3;
    g_wFh[i] = u;
}

// ---------------- K2b: w_off -> fp16 A-fragment prepack (18 rows padded to 32) ----------------
__global__ void k_prep_woff(const float* __restrict__ w) {
    int i = blockIdx.x * blockDim.x + threadIdx.x;
    if (i >= KK*8*2*32) return;
    int l   = i & 31;
    int ost = (i >> 5) & 1;
    int s   = (i >> 6) & 7;
    int tap = i >> 9;
    int o = ost*16 + (l >> 2);
    int c0 = s*16 + (l & 3)*2;
    float v00 = 0.f, v01 = 0.f, v08 = 0.f, v09 = 0.f;
    float v10 = 0.f, v11 = 0.f, v18 = 0.f, v19 = 0.f;
    if (o < 18) {
        const float* w0 = w + ((size_t)o*CI)*9 + tap;
        v00 = w0[c0*9]; v01 = w0[(c0+1)*9]; v08 = w0[(c0+8)*9]; v09 = w0[(c0+9)*9];
    }
    if (o + 8 < 18) {
        const float* w1 = w + ((size_t)(o+8)*CI)*9 + tap;
        v10 = w1[c0*9]; v11 = w1[(c0+1)*9]; v18 = w1[(c0+8)*9]; v19 = w1[(c0+9)*9];
    }
    __half2 a0 = __floats2half2_rn(v00, v01);
    __half2 a1 = __floats2half2_rn(v10, v11);
    __half2 a2 = __floats2half2_rn(v08, v09);
    __half2 a3 = __floats2half2_rn(v18, v19);
    uint4 u;
    u.x = *(uint32_t*)&a0; u.y = *(uint32_t*)&a1;
    u.z = *(uint32_t*)&a2; u.w = *(uint32_t*)&a3;
    g_wOffFh[i] = u;
}

// ---------------- K4: fused offset-conv + deformable sampling + f16 MMA + BN stats ----------------
// block = (h, b): 128 pixels x 128 out channels. 256 threads = 8 warps.
#define OFF_OFF  (2*BUFH*2)              // 2 buffers of BUFH halfs -> byte offset 74880
#define SMEM_K4  (OFF_OFF + 9216)        // + float[18][128] offsets

__global__ __launch_bounds__(256, 2) void k_main(const float* __restrict__ b_off) {
    extern __shared__ __align__(16) char smem[];
    __half* buf0 = (__half*)smem;
    __half* buf1 = buf0 + BUFH;
    float*  sOff = (float*)(smem + OFF_OFF);

    const int h   = blockIdx.x;
    const int b   = blockIdx.y;
    const int tid = threadIdx.x;
    const int wid = tid >> 5;
    const int l   = tid & 31;

    // ================= Phase A: offset conv (18 x 128) via m16n8k16 =================
    {
        const int wo = wid >> 2;          // 0..1 (o-stripe of 16)
        const int wp = wid & 3;           // 0..3 (32-px group)
        float accO[4][4];
#pragma unroll
        for (int t = 0; t < 4; t++)
#pragma unroll
            for (int j = 0; j < 4; j++) accO[t][j] = 0.f;

        for (int r = 0; r < 3; r++) {
            __half* halo = (r & 1) ? buf1 : buf0;
            const int yy = h - 1 + r;
            const bool yok = (yy >= 0 && yy < Hn);
            for (int i = tid; i < 130*16; i += 256) {
                int p = i >> 4, q = i & 15;
                int sx = p - 1;
                uint4 u = make_uint4(0u, 0u, 0u, 0u);
                if (yok && sx >= 0 && sx < Wn)
                    u = *(const uint4*)(g_xTh + (size_t)(b*HW + yy*Wn + sx)*CI + q*8);
                *(uint4*)(halo + p*CIPH + q*8) = u;
            }
            __syncthreads();
            const __half* bBaseO = halo + (wp*32 + (l >> 2))*CIPH + (l & 3)*4;
#pragma unroll
            for (int kx = 0; kx < 3; kx++) {
                int k = 3*r + kx;
                const uint4* aBase = g_wOffFh + ((k*8)*2 + wo)*32 + l;
                const __half* bShift = bBaseO + kx*CIPH;
#pragma unroll
                for (int s = 0; s < 8; s++) {
                    uint4 aF = aBase[s*64];
                    const __half* bp = bShift + s*16;
#pragma unroll
                    for (int t = 0; t < 4; t++) {
                        uint2 bv = *(const uint2*)(bp + t*8*CIPH);
                        mma_f16(accO[t], aF, bv.x, bv.y);
                    }
                }
            }
        }

        int o0  = wo*16 + (l >> 2);
        int px0 = wp*32 + 2*(l & 3);
        float bo0 = (o0     < 18) ? b_off[o0]     : 0.f;
        float bo1 = (o0 + 8 < 18) ? b_off[o0 + 8] : 0.f;
#pragma unroll
        for (int t = 0; t < 4; t++) {
            int px = px0 + t*8;
            if (o0 < 18) {
                sOff[o0*128 + px]     = accO[t][0] + bo0;
                sOff[o0*128 + px + 1] = accO[t][1] + bo0;
            }
            if (o0 + 8 < 18) {
                sOff[(o0 + 8)*128 + px]     = accO[t][2] + bo1;
                sOff[(o0 + 8)*128 + px + 1] = accO[t][3] + bo1;
            }
        }
    }
    __syncthreads();   // sOff ready; all Phase-A buffer reads complete

    // ================= Phase B: deformable sampling + main GEMM =================
    const int wm  = wid >> 1;
    const int wc  = wid & 1;

    float acc[2][8][4];
#pragma unroll
    for (int st = 0; st < 2; st++)
#pragma unroll
        for (int t = 0; t < 8; t++)
#pragma unroll
            for (int j = 0; j < 4; j++) acc[st][t][j] = 0.f;

    const int spix  = tid >> 3;           // sampler: pixel 0..31 (per pass)
    const int lane8 = tid & 7;

    for (int k = 0; k < KK; k++) {
        __half* sS = (k & 1) ? buf1 : buf0;
        const int ky = k / 3, kx = k % 3;
        const float* dyp = sOff + (2*k)*128;
        const float* dxp = sOff + (2*k + 1)*128;
#pragma unroll
        for (int pass = 0; pass < 4; pass++) {
            int px = pass*32 + spix;
            float dy = dyp[px];
            float dx = dxp[px];
            float ys = (float)(h - 1 + ky) + dy;
            float xs = (float)(px - 1 + kx) + dx;
            float y0f = floorf(ys), x0f = floorf(xs);
            float wy = ys - y0f, wx = xs - x0f;
            int y0 = (int)y0f, x0 = (int)x0f;
            int y1 = y0 + 1, x1 = x0 + 1;
            float vy0 = (y0 >= 0 && y0 < Hn) ? 1.f : 0.f;
            float vy1 = (y1 >= 0 && y1 < Hn) ? 1.f : 0.f;
            float vx0 = (x0 >= 0 && x0 < Wn) ? 1.f : 0.f;
            float vx1 = (x1 >= 0 && x1 < Wn) ? 1.f : 0.f;
            int y0c = min(max(y0, 0), Hn-1), y1c = min(max(y1, 0), Hn-1);
            int x0c = min(max(x0, 0), Wn-1), x1c = min(max(x1, 0), Wn-1);
            int base = b * HW;
            int i0 = (base + y0c*Wn + x0c)*CI;
            int i1 = (base + y0c*Wn + x1c)*CI;
            int i2 = (base + y1c*Wn + x0c)*CI;
            int i3 = (base + y1c*Wn + x1c)*CI;
            // bilinear weights in half2 broadcast (blend runs on the half pipe)
            __half2 W00 = __float2half2_rn((1.f - wy)*(1.f - wx)*vy0*vx0);
            __half2 W01 = __float2half2_rn((1.f - wy)*wx       *vy0*vx1);
            __half2 W10 = __float2half2_rn(wy       *(1.f - wx)*vy1*vx0);
            __half2 W11 = __float2half2_rn(wy       *wx        *vy1*vx1);
#pragma unroll
            for (int cc = 0; cc < CI; cc += 64) {
                int c = cc + lane8*8;     // 8 slots per lane
                uint4 u0 = *(const uint4*)(g_xTh + i0 + c);
                uint4 u1 = *(const uint4*)(g_xTh + i1 + c);
                uint4 u2 = *(const uint4*)(g_xTh + i2 + c);
                uint4 u3 = *(const uint4*)(g_xTh + i3 + c);
                uint4 outv;
#pragma unroll
                for (int j = 0; j < 4; j++) {
                    __half2 r = __hmul2(W11, ((const __half2*)&u3)[j]);
                    r = __hfma2(W10, ((const __half2*)&u2)[j], r);
                    r = __hfma2(W01, ((const __half2*)&u1)[j], r);
                    r = __hfma2(W00, ((const __half2*)&u0)[j], r);
                    ((__half2*)&outv)[j] = r;
                }
                *(uint4*)(sS + px*CIPH + c) = outv;
            }
        }
        __syncthreads();   // the ONLY barrier per tap

        // --- GEMM: 8 K=16 steps; per step 2 A-frag LDG.128 + 8 B LDS.64 ---
        const __half* bBase = sS + (wc*64 + (l >> 2))*CIPH + (l & 3)*4;
        const uint4* aBase = g_wFh + ((k*8)*8 + 2*wm)*32 + l;
#pragma unroll
        for (int s = 0; s < 8; s++) {
            uint4 aF0 = aBase[s*256];          // ostripe 2*wm
            uint4 aF1 = aBase[s*256 + 32];     // ostripe 2*wm + 1
            const __half* bp = bBase + s*16;
#pragma unroll
            for (int t = 0; t < 8; t++) {
                uint2 bv = *(const uint2*)(bp + t*8*CIPH);
                mma_f16(acc[0][t], aF0, bv.x, bv.y);
                mma_f16(acc[1][t], aF1, bv.x, bv.y);
            }
        }
    }

    // --- epilogue: D[o][pix] fragments -> g_convh (NCHW, fp16) ---
#pragma unroll
    for (int st = 0; st < 2; st++) {
        int o = 32*wm + st*16 + (l >> 2);
#pragma unroll
        for (int t = 0; t < 8; t++) {
            int px = wc*64 + t*8 + 2*(l & 3);
            __half* d = g_convh + ((size_t)(b*CO + o)*Hn + h)*Wn + px;
            *(__half2*)d          = __floats2half2_rn(acc[st][t][0], acc[st][t][1]);
            *(__half2*)(d + 8*HW) = __floats2half2_rn(acc[st][t][2], acc[st][t][3]);
        }
    }

    // --- fused BN stats: quad-reduce, atomic (from fp32 registers) ---
    {
        float s[4] = {0.f, 0.f, 0.f, 0.f};
        float q[4] = {0.f, 0.f, 0.f, 0.f};
#pragma unroll
        for (int st = 0; st < 2; st++)
#pragma unroll
            for (int t = 0; t < 8; t++) {
                float a0 = acc[st][t][0], a1 = acc[st][t][1];
                float a2 = acc[st][t][2], a3 = acc[st][t][3];
                s[2*st]   += a0 + a1;  q[2*st]   += a0*a0 + a1*a1;
                s[2*st+1] += a2 + a3;  q[2*st+1] += a2*a2 + a3*a3;
            }
#pragma unroll
        for (int d = 1; d < 4; d <<= 1)
#pragma unroll
            for (int j = 0; j < 4; j++) {
                s[j] += __shfl_xor_sync(0xffffffffu, s[j], d);
                q[j] += __shfl_xor_sync(0xffffffffu, q[j], d);
            }
        if ((l & 3) == 0) {
            int o0 = 32*wm + (l >> 2);
#pragma unroll
            for (int j = 0; j < 4; j++) {
                int o = o0 + 8*j;
                atomicAdd(&g_stat[o], s[j]);
                atomicAdd(&g_stat[CO + o], q[j]);
            }
        }
    }
}

// ---------------- K5: BN finalize (tiny) ----------------
__global__ void k_bn_finalize(const float* __restrict__ gamma,
                              const float* __restrict__ beta) {
    int o = threadIdx.x;
    float inv_n = 1.f / (float)(Bn*HW);
    float mean = g_stat[o] * inv_n;
    float var  = g_stat[CO + o] * inv_n - mean*mean;
    float r = rsqrtf(var + 0.001f);
    float sc = gamma[o] * r;
    g_scale[o] = sc;
    g_shift[o] = beta[o] - mean*sc;
}

// ---------------- K6: apply BN + ReLU (fp16 in, fp32 out) ----------------
__global__ void k_bn_apply(float* __restrict__ out) {
    int i = blockIdx.x * blockDim.x + threadIdx.x;   // 8-half chunk index
    int ch = (i >> 11) & 127;                        // plane = 16384 halfs = 2048 chunks
    uint4 u = ((const uint4*)g_convh)[i];
    float sc = g_scale[ch], sh = g_shift[ch];
    float4 o0, o1;
    float2 f;
    f = __half22float2(((const __half2*)&u)[0]);
    o0.x = fmaxf(fmaf(f.x, sc, sh), 0.f); o0.y = fmaxf(fmaf(f.y, sc, sh), 0.f);
    f = __half22float2(((const __half2*)&u)[1]);
    o0.z = fmaxf(fmaf(f.x, sc, sh), 0.f); o0.w = fmaxf(fmaf(f.y, sc, sh), 0.f);
    f = __half22float2(((const __half2*)&u)[2]);
    o1.x = fmaxf(fmaf(f.x, sc, sh), 0.f); o1.y = fmaxf(fmaf(f.y, sc, sh), 0.f);
    f = __half22float2(((const __half2*)&u)[3]);
    o1.z = fmaxf(fmaf(f.x, sc, sh), 0.f); o1.w = fmaxf(fmaf(f.y, sc, sh), 0.f);
    ((float4*)out)[2*i]     = o0;
    ((float4*)out)[2*i + 1] = o1;
}

// ---------------- launch ----------------
extern "C" void kernel_launch(void* const* d_in, const int* in_sizes, int n_in,
                              void* d_out, int out_size) {
    const float* x     = (const float*)d_in[0];
    const float* w_off = (const float*)d_in[1];
    const float* b_off = (const float*)d_in[2];
    const float* w_dcn = (const float*)d_in[3];
    const float* gamma = (const float*)d_in[4];
    const float* beta  = (const float*)d_in[5];
    float* out = (float*)d_out;

    cudaFuncSetAttribute(k_main, cudaFuncAttributeMaxDynamicSharedMemorySize, SMEM_K4);

    k_transpose_x<<<dim3(Wn/32, CI/32, Bn*Hn), dim3(32, 32)>>>(x);
    k_prep_w<<<(KK*8*8*32 + 255)/256, 256>>>(w_dcn);
    k_prep_woff<<<(KK*8*2*32 + 255)/256, 256>>>(w_off);
    k_main<<<dim3(Hn, Bn), 256, SMEM_K4>>>(b_off);
    k_bn_finalize<<<1, CO>>>(gamma, beta);
    k_bn_apply<<<(Bn*CO*HW/8)/256, 256>>>(out);
}